// round 1
// baseline (speedup 1.0000x reference)
#include <cuda_runtime.h>
#include <math.h>
#include <stdint.h>

// ---------------------------------------------------------------------------
// Problem constants
// ---------------------------------------------------------------------------
#define DIM   512
#define NHEAD 8
#define DHEAD 64
#define BATCH 8
#define LLAT  128
#define NCTX  4096
#define FFD   2048
#define ATT_SCALE 0.125f   // (512/8)^-0.5

// ---------------------------------------------------------------------------
// Scratch (single static device buffer; offsets in floats)
// ---------------------------------------------------------------------------
#define OFF_CN   0ull                               // 8*4096*512   = 16777216
#define OFF_KV   16777216ull                        // 8*4096*1024  = 33554432
#define OFF_XN   50331648ull                        // 8*128*512    = 524288
#define OFF_Q    50855936ull
#define OFF_AO   51380224ull
#define OFF_X1   51904512ull
#define OFF_X2   52428800ull
#define OFF_H    52953088ull                        // 8*128*4096   = 4194304
#define OFF_GG   57147392ull                        // 8*128*2048   = 2097152
#define OFF_PART 59244544ull                        // 8*8*128*8*66 = 4325376
#define SCRATCH_TOTAL 63569920ull

__device__ float g_scratch[SCRATCH_TOTAL];

// ---------------------------------------------------------------------------
// LayerNorm over last dim (=512). One block per row, 128 threads, float4.
// ---------------------------------------------------------------------------
__global__ __launch_bounds__(128) void ln_kernel(
    const float* __restrict__ x, const float* __restrict__ w,
    const float* __restrict__ b, float* __restrict__ out)
{
    int row = blockIdx.x;
    int t = threadIdx.x;
    const float4* xr = reinterpret_cast<const float4*>(x + (size_t)row * DIM);
    float4 v = xr[t];
    float s  = v.x + v.y + v.z + v.w;
    float ss = v.x*v.x + v.y*v.y + v.z*v.z + v.w*v.w;
    #pragma unroll
    for (int o = 16; o > 0; o >>= 1) {
        s  += __shfl_xor_sync(0xffffffffu, s,  o);
        ss += __shfl_xor_sync(0xffffffffu, ss, o);
    }
    __shared__ float rs[4], rss[4];
    int warp = t >> 5;
    if ((t & 31) == 0) { rs[warp] = s; rss[warp] = ss; }
    __syncthreads();
    s  = rs[0]  + rs[1]  + rs[2]  + rs[3];
    ss = rss[0] + rss[1] + rss[2] + rss[3];
    float mu  = s * (1.0f / DIM);
    float var = ss * (1.0f / DIM) - mu * mu;
    float inv = rsqrtf(var + 1e-5f);
    float4 wv = reinterpret_cast<const float4*>(w)[t];
    float4 bv = reinterpret_cast<const float4*>(b)[t];
    float4 o4;
    o4.x = (v.x - mu) * inv * wv.x + bv.x;
    o4.y = (v.y - mu) * inv * wv.y + bv.y;
    o4.z = (v.z - mu) * inv * wv.z + bv.z;
    o4.w = (v.w - mu) * inv * wv.w + bv.w;
    reinterpret_cast<float4*>(out + (size_t)row * DIM)[t] = o4;
}

// ---------------------------------------------------------------------------
// SGEMM: C[M,N] = A[M,K] @ W[K,N] (+ bias[n]) (+ res[M,N])
// Tiles 64x64x16, 256 threads, 4x4 register blocking, float4 I/O.
// All M,N,K here are multiples of 64/64/16.
// ---------------------------------------------------------------------------
template<bool BIAS, bool RES>
__global__ __launch_bounds__(256) void sgemm_kernel(
    const float* __restrict__ A, const float* __restrict__ W,
    const float* __restrict__ bias, const float* __restrict__ res,
    float* __restrict__ C, int M, int N, int K)
{
    __shared__ float As[16][64];
    __shared__ float Bs[16][64];
    int tid = threadIdx.x;
    int bm = blockIdx.y * 64;
    int bn = blockIdx.x * 64;
    int tx = tid & 15, ty = tid >> 4;
    int arow = tid >> 2,  acol = (tid & 3)  << 2;
    int brow = tid >> 4,  bcol = (tid & 15) << 2;
    const float* Ap = A + (size_t)(bm + arow) * K + acol;
    const float* Wp = W + (size_t)brow * N + bn + bcol;

    float acc[4][4];
    #pragma unroll
    for (int i = 0; i < 4; i++)
        #pragma unroll
        for (int j = 0; j < 4; j++) acc[i][j] = 0.0f;

    for (int k0 = 0; k0 < K; k0 += 16) {
        float4 a4 = *reinterpret_cast<const float4*>(Ap + k0);
        float4 b4 = *reinterpret_cast<const float4*>(Wp + (size_t)k0 * N);
        As[acol + 0][arow] = a4.x;
        As[acol + 1][arow] = a4.y;
        As[acol + 2][arow] = a4.z;
        As[acol + 3][arow] = a4.w;
        *reinterpret_cast<float4*>(&Bs[brow][bcol]) = b4;
        __syncthreads();
        #pragma unroll
        for (int k = 0; k < 16; k++) {
            float4 ra4 = *reinterpret_cast<const float4*>(&As[k][ty << 2]);
            float4 rb4 = *reinterpret_cast<const float4*>(&Bs[k][tx << 2]);
            float ra[4] = {ra4.x, ra4.y, ra4.z, ra4.w};
            float rb[4] = {rb4.x, rb4.y, rb4.z, rb4.w};
            #pragma unroll
            for (int i = 0; i < 4; i++)
                #pragma unroll
                for (int j = 0; j < 4; j++)
                    acc[i][j] += ra[i] * rb[j];
        }
        __syncthreads();
    }

    #pragma unroll
    for (int i = 0; i < 4; i++) {
        int r = bm + (ty << 2) + i;
        size_t off = (size_t)r * N + bn + (tx << 2);
        float4 v = make_float4(acc[i][0], acc[i][1], acc[i][2], acc[i][3]);
        if (BIAS) {
            float4 bb = *reinterpret_cast<const float4*>(bias + bn + (tx << 2));
            v.x += bb.x; v.y += bb.y; v.z += bb.z; v.w += bb.w;
        }
        if (RES) {
            float4 rr = *reinterpret_cast<const float4*>(res + off);
            v.x += rr.x; v.y += rr.y; v.z += rr.z; v.w += rr.w;
        }
        *reinterpret_cast<float4*>(C + off) = v;
    }
}

// ---------------------------------------------------------------------------
// Flash attention with split-KV partials.
// Q:  [B, 128, 512]  (col = h*64+d)
// KV: [B, Nk, 1024]  (K at col h*64+d, V at col 512+h*64+d)
// grid: (B*H, 128/64, nsplit), block 128 (2 threads per query row).
// partial: [B, H, 128, nsplit, 66] = (m, l, acc[64])
// ---------------------------------------------------------------------------
__global__ __launch_bounds__(128) void flash_kernel(
    const float* __restrict__ Q, const float* __restrict__ KV,
    float* __restrict__ part, int Nk, int nsplit)
{
    const int TJ = 32;
    __shared__ float Ks[TJ][DHEAD];
    __shared__ float Vs[TJ][DHEAD];

    int bh = blockIdx.x;
    int b = bh >> 3, h = bh & 7;
    int r0 = blockIdx.y * 64;
    int split = blockIdx.z;
    int chunk = Nk / nsplit;
    int j0 = split * chunk;
    int t = threadIdx.x;
    int row = r0 + (t >> 1);
    int half = t & 1;

    const float* qp = Q + ((size_t)(b * LLAT + row)) * DIM + h * DHEAD + half * 32;
    float qr[32];
    #pragma unroll
    for (int c = 0; c < 8; c++) {
        float4 q4 = reinterpret_cast<const float4*>(qp)[c];
        qr[c*4+0] = q4.x; qr[c*4+1] = q4.y; qr[c*4+2] = q4.z; qr[c*4+3] = q4.w;
    }
    float acc[32];
    #pragma unroll
    for (int c = 0; c < 32; c++) acc[c] = 0.0f;
    float m = -INFINITY, l = 0.0f;

    const float* kvbase = KV + (size_t)b * Nk * (2 * DIM);

    for (int jt = 0; jt < chunk; jt += TJ) {
        __syncthreads();
        #pragma unroll
        for (int i = 0; i < 4; i++) {
            int f  = i * 128 + t;      // 0..511 float4 slots
            int j  = f >> 4;           // key in tile
            int c4 = f & 15;           // float4 col
            const float* src = kvbase + (size_t)(j0 + jt + j) * (2 * DIM) + h * DHEAD + c4 * 4;
            float4 kk = *reinterpret_cast<const float4*>(src);
            float4 vv = *reinterpret_cast<const float4*>(src + DIM);
            *reinterpret_cast<float4*>(&Ks[j][c4 * 4]) = kk;
            *reinterpret_cast<float4*>(&Vs[j][c4 * 4]) = vv;
        }
        __syncthreads();
        #pragma unroll 2
        for (int j = 0; j < TJ; j++) {
            float s = 0.0f;
            const float4* kp = reinterpret_cast<const float4*>(&Ks[j][half * 32]);
            #pragma unroll
            for (int c = 0; c < 8; c++) {
                float4 kk = kp[c];
                s += qr[c*4+0]*kk.x + qr[c*4+1]*kk.y + qr[c*4+2]*kk.z + qr[c*4+3]*kk.w;
            }
            s += __shfl_xor_sync(0xffffffffu, s, 1);
            s *= ATT_SCALE;
            float mold = m;
            m = fmaxf(m, s);
            float corr = __expf(mold - m);
            float p    = __expf(s - m);
            l = l * corr + p;
            const float4* vp = reinterpret_cast<const float4*>(&Vs[j][half * 32]);
            #pragma unroll
            for (int c = 0; c < 8; c++) {
                float4 vv = vp[c];
                acc[c*4+0] = acc[c*4+0]*corr + p*vv.x;
                acc[c*4+1] = acc[c*4+1]*corr + p*vv.y;
                acc[c*4+2] = acc[c*4+2]*corr + p*vv.z;
                acc[c*4+3] = acc[c*4+3]*corr + p*vv.w;
            }
        }
    }

    size_t base = ((((size_t)(b * NHEAD + h) * LLAT + row) * nsplit) + split) * 66;
    if (half == 0) { part[base] = m; part[base + 1] = l; }
    #pragma unroll
    for (int c = 0; c < 32; c++) part[base + 2 + half * 32 + c] = acc[c];
}

// ---------------------------------------------------------------------------
// Combine split-KV partials -> attn output [B, 128, 512] (col h*64+d)
// grid: B*H*128 blocks, 64 threads (one per head dim).
// ---------------------------------------------------------------------------
__global__ __launch_bounds__(64) void combine_kernel(
    const float* __restrict__ part, float* __restrict__ out, int nsplit)
{
    int idx = blockIdx.x;              // (b*H + h)*128 + i
    int i  = idx & (LLAT - 1);
    int bh = idx >> 7;
    int b = bh >> 3, h = bh & 7;
    int d = threadIdx.x;
    size_t base = (size_t)idx * nsplit * 66;
    float M = -INFINITY;
    for (int s = 0; s < nsplit; s++) M = fmaxf(M, part[base + (size_t)s * 66]);
    float L = 0.0f, o = 0.0f;
    for (int s = 0; s < nsplit; s++) {
        float a = __expf(part[base + (size_t)s * 66] - M);
        L += a * part[base + (size_t)s * 66 + 1];
        o += a * part[base + (size_t)s * 66 + 2 + d];
    }
    out[((size_t)(b * LLAT + i)) * DIM + h * DHEAD + d] = o / L;
}

// ---------------------------------------------------------------------------
// GEGLU: out[row, c] = h[row, c] * gelu(h[row, FFD + c]), exact erf GELU.
// h: [1024, 2*FFD], out: [1024, FFD]
// ---------------------------------------------------------------------------
__global__ __launch_bounds__(256) void geglu_kernel(
    const float* __restrict__ hbuf, float* __restrict__ out)
{
    int idx = blockIdx.x * blockDim.x + threadIdx.x;   // over 1024*FFD
    int row = idx >> 11;        // /2048
    int c   = idx & 2047;
    float a = hbuf[(size_t)row * (2 * FFD) + c];
    float g = hbuf[(size_t)row * (2 * FFD) + FFD + c];
    float ge = 0.5f * g * (1.0f + erff(g * 0.70710678118654752f));
    out[idx] = a * ge;
}

// ---------------------------------------------------------------------------
// Host orchestration
// ---------------------------------------------------------------------------
extern "C" void kernel_launch(void* const* d_in, const int* in_sizes, int n_in,
                              void* d_out, int out_size)
{
    (void)in_sizes; (void)n_in; (void)out_size;
    const float* context = (const float*)d_in[0];
    const float* latents = (const float*)d_in[1];
    const float* ca_ln_w  = (const float*)d_in[2];
    const float* ca_ln_b  = (const float*)d_in[3];
    const float* ca_lnc_w = (const float*)d_in[4];
    const float* ca_lnc_b = (const float*)d_in[5];
    const float* ca_wq  = (const float*)d_in[6];
    const float* ca_wkv = (const float*)d_in[7];
    const float* ca_wo  = (const float*)d_in[8];
    const float* ca_bo  = (const float*)d_in[9];
    const float* cf_ln_w = (const float*)d_in[10];
    const float* cf_ln_b = (const float*)d_in[11];
    const float* cf_w1 = (const float*)d_in[12];
    const float* cf_b1 = (const float*)d_in[13];
    const float* cf_w2 = (const float*)d_in[14];
    const float* cf_b2 = (const float*)d_in[15];
    const float* sa_ln_w = (const float*)d_in[16];
    const float* sa_ln_b = (const float*)d_in[17];
    const float* sa_wq  = (const float*)d_in[18];
    const float* sa_wkv = (const float*)d_in[19];
    const float* sa_wo  = (const float*)d_in[20];
    const float* sa_bo  = (const float*)d_in[21];
    const float* lf_ln_w = (const float*)d_in[22];
    const float* lf_ln_b = (const float*)d_in[23];
    const float* lf_w1 = (const float*)d_in[24];
    const float* lf_b1 = (const float*)d_in[25];
    const float* lf_w2 = (const float*)d_in[26];
    const float* lf_b2 = (const float*)d_in[27];

    void* sp = nullptr;
    cudaGetSymbolAddress(&sp, g_scratch);
    float* S    = (float*)sp;
    float* cn   = S + OFF_CN;
    float* kvb  = S + OFF_KV;
    float* xn   = S + OFF_XN;
    float* qb   = S + OFF_Q;
    float* aob  = S + OFF_AO;
    float* x1   = S + OFF_X1;
    float* x2   = S + OFF_X2;
    float* hb   = S + OFF_H;
    float* ggb  = S + OFF_GG;
    float* pb   = S + OFF_PART;
    float* x3   = xn + 0;  // note: xn gets overwritten per-stage; x3 needs its own slot
    // reuse cn tail region for x3 (cn is dead after the KV projection)
    x3 = cn;

    const int rowsL = BATCH * LLAT;        // 1024
    const int rowsC = BATCH * NCTX;        // 32768

    // ---- cross attention ----
    ln_kernel<<<rowsL, 128>>>(latents, ca_ln_w, ca_ln_b, xn);
    ln_kernel<<<rowsC, 128>>>(context, ca_lnc_w, ca_lnc_b, cn);
    sgemm_kernel<false,false><<<dim3(8, 16),  256>>>(xn, ca_wq,  nullptr, nullptr, qb,  rowsL, 512, 512);
    sgemm_kernel<false,false><<<dim3(16, 512),256>>>(cn, ca_wkv, nullptr, nullptr, kvb, rowsC, 1024, 512);
    flash_kernel<<<dim3(64, 2, 8), 128>>>(qb, kvb, pb, NCTX, 8);
    combine_kernel<<<8192, 64>>>(pb, aob, 8);
    sgemm_kernel<true,true><<<dim3(8, 16), 256>>>(aob, ca_wo, ca_bo, latents, x1, rowsL, 512, 512);

    // ---- cross FFN (GEGLU) ----
    ln_kernel<<<rowsL, 128>>>(x1, cf_ln_w, cf_ln_b, xn);
    sgemm_kernel<true,false><<<dim3(64, 16), 256>>>(xn, cf_w1, cf_b1, nullptr, hb, rowsL, 4096, 512);
    geglu_kernel<<<8192, 256>>>(hb, ggb);
    sgemm_kernel<true,true><<<dim3(8, 16), 256>>>(ggb, cf_w2, cf_b2, x1, x2, rowsL, 512, 2048);

    // ---- latent self-attention ----
    ln_kernel<<<rowsL, 128>>>(x2, sa_ln_w, sa_ln_b, xn);
    sgemm_kernel<false,false><<<dim3(8, 16),  256>>>(xn, sa_wq,  nullptr, nullptr, qb,  rowsL, 512, 512);
    sgemm_kernel<false,false><<<dim3(16, 16), 256>>>(xn, sa_wkv, nullptr, nullptr, kvb, rowsL, 1024, 512);
    flash_kernel<<<dim3(64, 2, 1), 128>>>(qb, kvb, pb, LLAT, 1);
    combine_kernel<<<8192, 64>>>(pb, aob, 1);
    sgemm_kernel<true,true><<<dim3(8, 16), 256>>>(aob, sa_wo, sa_bo, x2, x3, rowsL, 512, 512);

    // ---- latent FFN (GEGLU) ----
    ln_kernel<<<rowsL, 128>>>(x3, lf_ln_w, lf_ln_b, xn);
    sgemm_kernel<true,false><<<dim3(64, 16), 256>>>(xn, lf_w1, lf_b1, nullptr, hb, rowsL, 4096, 512);
    geglu_kernel<<<8192, 256>>>(hb, ggb);
    sgemm_kernel<true,true><<<dim3(8, 16), 256>>>(ggb, lf_w2, lf_b2, x3, (float*)d_out, rowsL, 512, 2048);
}

// round 3
// speedup vs baseline: 1.6412x; 1.6412x over previous
#include <cuda_runtime.h>
#include <cuda_bf16.h>
#include <math.h>
#include <stdint.h>

// ---------------------------------------------------------------------------
// Problem constants
// ---------------------------------------------------------------------------
#define DIM   512
#define NHEAD 8
#define DHEAD 64
#define BATCH 8
#define LLAT  128
#define NCTX  4096
#define FFD   2048
#define ATT_SCALE 0.125f

typedef __nv_bfloat16 bf16;

// ---------------------------------------------------------------------------
// Scratch (bytes, all offsets 1024-aligned)
// ---------------------------------------------------------------------------
#define SB_KVB   0ull            // f32 [32768,1024]
#define SB_HB    134217728ull    // f32 [1024,4096]
#define SB_PART  150994944ull    // f32 partials
#define SB_CNH   168296448ull    // bf16 [32768,512]
#define SB_CNL   201850880ull
#define SB_WHI   235405312ull    // bf16 packed transposed weights
#define SB_WLO   252182528ull
#define SB_XNH   268959744ull    // bf16 [1024,512]
#define SB_XNL   270008320ull
#define SB_QB    271056896ull    // f32 [1024,512]
#define SB_AOBH  273154048ull
#define SB_AOBL  274202624ull
#define SB_GGH   275251200ull    // bf16 [1024,2048]
#define SB_GGL   279445504ull
#define SB_X1    283639808ull
#define SB_X2    285736960ull
#define SB_X3    287834112ull
#define SCRATCH_BYTES 289931264ull

__device__ __align__(1024) unsigned char g_scratch[SCRATCH_BYTES];

// Packed transposed-weight element offsets (bf16 elements)
#define WO_CAQ   0ull
#define WO_CAKV  262144ull
#define WO_CAO   786432ull
#define WO_CF1   1048576ull
#define WO_CF2   3145728ull
#define WO_SAQ   4194304ull
#define WO_SAKV  4456448ull
#define WO_SAO   4980736ull
#define WO_LF1   5242880ull
#define WO_LF2   7340032ull

// ---------------------------------------------------------------------------
// Low-level helpers (baseline ISA only: ldmatrix / mma.sync / cp.async)
// ---------------------------------------------------------------------------
__device__ __forceinline__ uint32_t smem_u32(const void* p) {
    uint32_t a;
    asm("{ .reg .u64 t; cvta.to.shared.u64 t, %1; cvt.u32.u64 %0, t; }" : "=r"(a) : "l"(p));
    return a;
}
__device__ __forceinline__ void cp16(uint32_t dst, const void* src) {
    asm volatile("cp.async.cg.shared.global [%0], [%1], 16;" :: "r"(dst), "l"(src) : "memory");
}
#define CP_COMMIT() asm volatile("cp.async.commit_group;" ::: "memory")
#define CP_WAIT(n)  asm volatile("cp.async.wait_group %0;" :: "n"(n) : "memory")

__device__ __forceinline__ void ldm_x4(uint32_t* r, uint32_t addr) {
    asm volatile("ldmatrix.sync.aligned.m8n8.x4.shared.b16 {%0,%1,%2,%3}, [%4];"
        : "=r"(r[0]), "=r"(r[1]), "=r"(r[2]), "=r"(r[3]) : "r"(addr));
}
__device__ __forceinline__ void mma16816(float* c, const uint32_t* a, uint32_t b0, uint32_t b1) {
    asm volatile("mma.sync.aligned.m16n8k16.row.col.f32.bf16.bf16.f32 "
        "{%0,%1,%2,%3}, {%4,%5,%6,%7}, {%8,%9}, {%0,%1,%2,%3};"
        : "+f"(c[0]), "+f"(c[1]), "+f"(c[2]), "+f"(c[3])
        : "r"(a[0]), "r"(a[1]), "r"(a[2]), "r"(a[3]), "r"(b0), "r"(b1));
}

// ---------------------------------------------------------------------------
// Tensor-core GEMM: C[M,N] = (Ahi+Alo)[M,K] @ (Bhi+Blo)[N,K]^T (+bias)(+res)
// CTA 128x128, K-step 32, 8 warps (4m x 2n), warp tile 32x64, cp.async x2 stages.
// ---------------------------------------------------------------------------
#define ROW_ELEMS 40                       // 32 + 8 pad (bf16)
#define OP_BYTES  (128 * ROW_ELEMS * 2)    // 10240
#define STAGE_BYTES (4 * OP_BYTES)         // 40960: Ahi|Alo|Bhi|Blo
#define MM_SMEM (2 * STAGE_BYTES)          // 81920

__device__ __forceinline__ void mm_load_stage(
    uint32_t sbase, const bf16* __restrict__ Ahi, const bf16* __restrict__ Alo,
    const bf16* __restrict__ Bhi, const bf16* __restrict__ Blo,
    int bm, int bn, int K, int k0, int tid)
{
    const bf16* bases[4] = {Ahi, Alo, Bhi, Blo};
    #pragma unroll
    for (int o = 0; o < 4; o++) {
        const bf16* base = bases[o];
        int g0 = (o < 2) ? bm : bn;
        #pragma unroll
        for (int h = 0; h < 2; h++) {
            int idx = h * 256 + tid;          // 0..511 16B chunks
            int row = idx >> 2, c = idx & 3;
            cp16(sbase + o * OP_BYTES + row * (ROW_ELEMS * 2) + c * 16,
                 base + (size_t)(g0 + row) * K + k0 + c * 8);
        }
    }
}

__device__ __forceinline__ void mm_compute_stage(
    uint32_t sbase, float (&acc)[2][8][4], int wm, int wn, int lane)
{
    const uint32_t aAh = sbase;
    const uint32_t aAl = sbase + OP_BYTES;
    const uint32_t aBh = sbase + 2 * OP_BYTES;
    const uint32_t aBl = sbase + 3 * OP_BYTES;
    // ldmatrix x4 lane->address mapping
    int arow = lane & 15;            // A: lanes 0-7 m0-7(k0), 8-15 m8-15(k0), 16-23 m0-7(k8), 24-31 m8-15(k8)
    int acolg = lane >> 4;
    int brow = ((lane >> 4) << 3) + (lane & 7);  // B: n within 16-block
    int bcolg = (lane >> 3) & 1;
    #pragma unroll
    for (int kk = 0; kk < 2; kk++) {
        int k0 = kk * 16;
        uint32_t ah[2][4], al[2][4];
        #pragma unroll
        for (int mb = 0; mb < 2; mb++) {
            uint32_t off = (uint32_t)((wm * 32 + mb * 16 + arow) * ROW_ELEMS + k0 + acolg * 8) * 2;
            ldm_x4(ah[mb], aAh + off);
            ldm_x4(al[mb], aAl + off);
        }
        uint32_t bh[4][4], bl[4][4];
        #pragma unroll
        for (int j = 0; j < 4; j++) {
            uint32_t off = (uint32_t)((wn * 64 + j * 16 + brow) * ROW_ELEMS + k0 + bcolg * 8) * 2;
            ldm_x4(bh[j], aBh + off);
            ldm_x4(bl[j], aBl + off);
        }
        #pragma unroll
        for (int mb = 0; mb < 2; mb++) {
            #pragma unroll
            for (int j = 0; j < 4; j++) {
                #pragma unroll
                for (int p = 0; p < 2; p++) {
                    float* c = acc[mb][j * 2 + p];
                    uint32_t b0 = bh[j][p * 2], b1 = bh[j][p * 2 + 1];
                    mma16816(c, ah[mb], b0, b1);                       // hi*hi
                    mma16816(c, ah[mb], bl[j][p * 2], bl[j][p * 2 + 1]); // hi*lo
                    mma16816(c, al[mb], b0, b1);                       // lo*hi
                }
            }
        }
    }
}

template<bool BIAS, bool RES>
__global__ __launch_bounds__(256) void mmgemm_kernel(
    const bf16* __restrict__ Ahi, const bf16* __restrict__ Alo,
    const bf16* __restrict__ Bhi, const bf16* __restrict__ Blo,
    const float* __restrict__ bias, const float* __restrict__ res,
    float* __restrict__ C, int M, int N, int K)
{
    extern __shared__ __align__(128) char smem[];
    uint32_t sb = smem_u32(smem);
    int tid = threadIdx.x;
    int wid = tid >> 5, lane = tid & 31;
    int wm = wid >> 1, wn = wid & 1;
    int bm = blockIdx.y * 128, bn = blockIdx.x * 128;

    float acc[2][8][4];
    #pragma unroll
    for (int a = 0; a < 2; a++)
        #pragma unroll
        for (int b = 0; b < 8; b++)
            #pragma unroll
            for (int c = 0; c < 4; c++) acc[a][b][c] = 0.0f;

    const int NC = K >> 5;
    mm_load_stage(sb, Ahi, Alo, Bhi, Blo, bm, bn, K, 0, tid);
    CP_COMMIT();
    for (int c = 0; c < NC; c++) {
        if (c + 1 < NC) {
            mm_load_stage(sb + ((c + 1) & 1) * STAGE_BYTES, Ahi, Alo, Bhi, Blo,
                          bm, bn, K, (c + 1) << 5, tid);
            CP_COMMIT();
            CP_WAIT(1);
        } else {
            CP_WAIT(0);
        }
        __syncthreads();
        mm_compute_stage(sb + (c & 1) * STAGE_BYTES, acc, wm, wn, lane);
        __syncthreads();
    }

    // epilogue
    int lane4 = lane >> 2;
    int lane2 = (lane & 3) << 1;
    #pragma unroll
    for (int mb = 0; mb < 2; mb++) {
        int r0 = bm + wm * 32 + mb * 16 + lane4;
        #pragma unroll
        for (int nb = 0; nb < 8; nb++) {
            int cc = bn + wn * 64 + nb * 8 + lane2;
            float* a = acc[mb][nb];
            float2 v0 = make_float2(a[0], a[1]);
            float2 v1 = make_float2(a[2], a[3]);
            if (BIAS) {
                float2 bb = *reinterpret_cast<const float2*>(bias + cc);
                v0.x += bb.x; v0.y += bb.y; v1.x += bb.x; v1.y += bb.y;
            }
            size_t o0 = (size_t)r0 * N + cc;
            size_t o1 = (size_t)(r0 + 8) * N + cc;
            if (RES) {
                float2 rr = *reinterpret_cast<const float2*>(res + o0);
                v0.x += rr.x; v0.y += rr.y;
                rr = *reinterpret_cast<const float2*>(res + o1);
                v1.x += rr.x; v1.y += rr.y;
            }
            *reinterpret_cast<float2*>(C + o0) = v0;
            *reinterpret_cast<float2*>(C + o1) = v1;
        }
    }
}

// ---------------------------------------------------------------------------
// LayerNorm (last dim 512) -> hi/lo bf16 split
// ---------------------------------------------------------------------------
__global__ __launch_bounds__(128) void ln_bf16_kernel(
    const float* __restrict__ x, const float* __restrict__ w,
    const float* __restrict__ b, bf16* __restrict__ ohi, bf16* __restrict__ olo)
{
    int row = blockIdx.x;
    int t = threadIdx.x;
    float4 v = reinterpret_cast<const float4*>(x + (size_t)row * DIM)[t];
    float s  = v.x + v.y + v.z + v.w;
    float ss = v.x*v.x + v.y*v.y + v.z*v.z + v.w*v.w;
    #pragma unroll
    for (int o = 16; o > 0; o >>= 1) {
        s  += __shfl_xor_sync(0xffffffffu, s,  o);
        ss += __shfl_xor_sync(0xffffffffu, ss, o);
    }
    __shared__ float rs[4], rss[4];
    int warp = t >> 5;
    if ((t & 31) == 0) { rs[warp] = s; rss[warp] = ss; }
    __syncthreads();
    s  = rs[0] + rs[1] + rs[2] + rs[3];
    ss = rss[0] + rss[1] + rss[2] + rss[3];
    float mu  = s * (1.0f / DIM);
    float var = ss * (1.0f / DIM) - mu * mu;
    float inv = rsqrtf(var + 1e-5f);
    float4 wv = reinterpret_cast<const float4*>(w)[t];
    float4 bv = reinterpret_cast<const float4*>(b)[t];
    float y[4];
    y[0] = (v.x - mu) * inv * wv.x + bv.x;
    y[1] = (v.y - mu) * inv * wv.y + bv.y;
    y[2] = (v.z - mu) * inv * wv.z + bv.z;
    y[3] = (v.w - mu) * inv * wv.w + bv.w;
    size_t base = (size_t)row * DIM + t * 4;
    #pragma unroll
    for (int i = 0; i < 4; i++) {
        bf16 h = __float2bfloat16(y[i]);
        ohi[base + i] = h;
        olo[base + i] = __float2bfloat16(y[i] - __bfloat162float(h));
    }
}

// ---------------------------------------------------------------------------
// Weight convert + transpose: W[K,N] f32 -> hi/lo bf16 [N,K]
// ---------------------------------------------------------------------------
__global__ __launch_bounds__(256) void wconv_kernel(
    const float* __restrict__ W, bf16* __restrict__ hi, bf16* __restrict__ lo,
    int K, int N)
{
    __shared__ float tile[32][33];
    int tx = threadIdx.x, ty = threadIdx.y;
    int x = blockIdx.x * 32 + tx;
    int y0 = blockIdx.y * 32;
    #pragma unroll
    for (int j = ty; j < 32; j += 8)
        tile[j][tx] = W[(size_t)(y0 + j) * N + x];
    __syncthreads();
    #pragma unroll
    for (int j = ty; j < 32; j += 8) {
        int n = blockIdx.x * 32 + j;
        int k = y0 + tx;
        float v = tile[tx][j];
        bf16 h = __float2bfloat16(v);
        hi[(size_t)n * K + k] = h;
        lo[(size_t)n * K + k] = __float2bfloat16(v - __bfloat162float(h));
    }
}

// ---------------------------------------------------------------------------
// Flash attention (fp32, split-KV)
// ---------------------------------------------------------------------------
__global__ __launch_bounds__(128) void flash_kernel(
    const float* __restrict__ Q, const float* __restrict__ KV,
    float* __restrict__ part, int Nk, int nsplit)
{
    const int TJ = 32;
    __shared__ float Ks[TJ][DHEAD];
    __shared__ float Vs[TJ][DHEAD];

    int bh = blockIdx.x;
    int b = bh >> 3, h = bh & 7;
    int r0 = blockIdx.y * 64;
    int split = blockIdx.z;
    int chunk = Nk / nsplit;
    int j0 = split * chunk;
    int t = threadIdx.x;
    int row = r0 + (t >> 1);
    int half = t & 1;

    const float* qp = Q + ((size_t)(b * LLAT + row)) * DIM + h * DHEAD + half * 32;
    float qr[32];
    #pragma unroll
    for (int c = 0; c < 8; c++) {
        float4 q4 = reinterpret_cast<const float4*>(qp)[c];
        qr[c*4+0] = q4.x; qr[c*4+1] = q4.y; qr[c*4+2] = q4.z; qr[c*4+3] = q4.w;
    }
    float acc[32];
    #pragma unroll
    for (int c = 0; c < 32; c++) acc[c] = 0.0f;
    float m = -INFINITY, l = 0.0f;

    const float* kvbase = KV + (size_t)b * Nk * (2 * DIM);

    for (int jt = 0; jt < chunk; jt += TJ) {
        __syncthreads();
        #pragma unroll
        for (int i = 0; i < 4; i++) {
            int f  = i * 128 + t;
            int j  = f >> 4;
            int c4 = f & 15;
            const float* src = kvbase + (size_t)(j0 + jt + j) * (2 * DIM) + h * DHEAD + c4 * 4;
            float4 kk = *reinterpret_cast<const float4*>(src);
            float4 vv = *reinterpret_cast<const float4*>(src + DIM);
            *reinterpret_cast<float4*>(&Ks[j][c4 * 4]) = kk;
            *reinterpret_cast<float4*>(&Vs[j][c4 * 4]) = vv;
        }
        __syncthreads();
        #pragma unroll 2
        for (int j = 0; j < TJ; j++) {
            float s = 0.0f;
            const float4* kp = reinterpret_cast<const float4*>(&Ks[j][half * 32]);
            #pragma unroll
            for (int c = 0; c < 8; c++) {
                float4 kk = kp[c];
                s += qr[c*4+0]*kk.x + qr[c*4+1]*kk.y + qr[c*4+2]*kk.z + qr[c*4+3]*kk.w;
            }
            s += __shfl_xor_sync(0xffffffffu, s, 1);
            s *= ATT_SCALE;
            float mold = m;
            m = fmaxf(m, s);
            float corr = __expf(mold - m);
            float p    = __expf(s - m);
            l = l * corr + p;
            const float4* vp = reinterpret_cast<const float4*>(&Vs[j][half * 32]);
            #pragma unroll
            for (int c = 0; c < 8; c++) {
                float4 vv = vp[c];
                acc[c*4+0] = acc[c*4+0]*corr + p*vv.x;
                acc[c*4+1] = acc[c*4+1]*corr + p*vv.y;
                acc[c*4+2] = acc[c*4+2]*corr + p*vv.z;
                acc[c*4+3] = acc[c*4+3]*corr + p*vv.w;
            }
        }
    }

    size_t base = ((((size_t)(b * NHEAD + h) * LLAT + row) * nsplit) + split) * 66;
    if (half == 0) { part[base] = m; part[base + 1] = l; }
    #pragma unroll
    for (int c = 0; c < 32; c++) part[base + 2 + half * 32 + c] = acc[c];
}

// ---------------------------------------------------------------------------
// Combine split-KV partials -> hi/lo bf16 attention output
// ---------------------------------------------------------------------------
__global__ __launch_bounds__(64) void combine_bf16_kernel(
    const float* __restrict__ part, bf16* __restrict__ ohi, bf16* __restrict__ olo,
    int nsplit)
{
    int idx = blockIdx.x;
    int i  = idx & (LLAT - 1);
    int bh = idx >> 7;
    int b = bh >> 3, h = bh & 7;
    int d = threadIdx.x;
    size_t base = (size_t)idx * nsplit * 66;
    float M = -INFINITY;
    for (int s = 0; s < nsplit; s++) M = fmaxf(M, part[base + (size_t)s * 66]);
    float L = 0.0f, o = 0.0f;
    for (int s = 0; s < nsplit; s++) {
        float a = __expf(part[base + (size_t)s * 66] - M);
        L += a * part[base + (size_t)s * 66 + 1];
        o += a * part[base + (size_t)s * 66 + 2 + d];
    }
    float y = o / L;
    size_t off = ((size_t)(b * LLAT + i)) * DIM + h * DHEAD + d;
    bf16 hv = __float2bfloat16(y);
    ohi[off] = hv;
    olo[off] = __float2bfloat16(y - __bfloat162float(hv));
}

// ---------------------------------------------------------------------------
// GEGLU (exact erf) -> hi/lo bf16
// ---------------------------------------------------------------------------
__global__ __launch_bounds__(256) void geglu_bf16_kernel(
    const float* __restrict__ hbuf, bf16* __restrict__ ohi, bf16* __restrict__ olo)
{
    int idx = blockIdx.x * blockDim.x + threadIdx.x;
    int row = idx >> 11;
    int c   = idx & 2047;
    float a = hbuf[(size_t)row * (2 * FFD) + c];
    float g = hbuf[(size_t)row * (2 * FFD) + FFD + c];
    float y = a * (0.5f * g * (1.0f + erff(g * 0.70710678118654752f)));
    bf16 hv = __float2bfloat16(y);
    ohi[idx] = hv;
    olo[idx] = __float2bfloat16(y - __bfloat162float(hv));
}

// ---------------------------------------------------------------------------
// Host orchestration
// ---------------------------------------------------------------------------
extern "C" void kernel_launch(void* const* d_in, const int* in_sizes, int n_in,
                              void* d_out, int out_size)
{
    (void)in_sizes; (void)n_in; (void)out_size;
    const float* context = (const float*)d_in[0];
    const float* latents = (const float*)d_in[1];
    const float* ca_ln_w  = (const float*)d_in[2];
    const float* ca_ln_b  = (const float*)d_in[3];
    const float* ca_lnc_w = (const float*)d_in[4];
    const float* ca_lnc_b = (const float*)d_in[5];
    const float* ca_wq  = (const float*)d_in[6];
    const float* ca_wkv = (const float*)d_in[7];
    const float* ca_wo  = (const float*)d_in[8];
    const float* ca_bo  = (const float*)d_in[9];
    const float* cf_ln_w = (const float*)d_in[10];
    const float* cf_ln_b = (const float*)d_in[11];
    const float* cf_w1 = (const float*)d_in[12];
    const float* cf_b1 = (const float*)d_in[13];
    const float* cf_w2 = (const float*)d_in[14];
    const float* cf_b2 = (const float*)d_in[15];
    const float* sa_ln_w = (const float*)d_in[16];
    const float* sa_ln_b = (const float*)d_in[17];
    const float* sa_wq  = (const float*)d_in[18];
    const float* sa_wkv = (const float*)d_in[19];
    const float* sa_wo  = (const float*)d_in[20];
    const float* sa_bo  = (const float*)d_in[21];
    const float* lf_ln_w = (const float*)d_in[22];
    const float* lf_ln_b = (const float*)d_in[23];
    const float* lf_w1 = (const float*)d_in[24];
    const float* lf_b1 = (const float*)d_in[25];
    const float* lf_w2 = (const float*)d_in[26];
    const float* lf_b2 = (const float*)d_in[27];

    void* sp = nullptr;
    cudaGetSymbolAddress(&sp, g_scratch);
    unsigned char* S = (unsigned char*)sp;
    float* kvb  = (float*)(S + SB_KVB);
    float* hb   = (float*)(S + SB_HB);
    float* pb   = (float*)(S + SB_PART);
    bf16* cnh   = (bf16*)(S + SB_CNH);
    bf16* cnl   = (bf16*)(S + SB_CNL);
    bf16* whi   = (bf16*)(S + SB_WHI);
    bf16* wlo   = (bf16*)(S + SB_WLO);
    bf16* xnh   = (bf16*)(S + SB_XNH);
    bf16* xnl   = (bf16*)(S + SB_XNL);
    float* qb   = (float*)(S + SB_QB);
    bf16* aobh  = (bf16*)(S + SB_AOBH);
    bf16* aobl  = (bf16*)(S + SB_AOBL);
    bf16* ggh   = (bf16*)(S + SB_GGH);
    bf16* ggl   = (bf16*)(S + SB_GGL);
    float* x1   = (float*)(S + SB_X1);
    float* x2   = (float*)(S + SB_X2);
    float* x3   = (float*)(S + SB_X3);

    cudaFuncSetAttribute(mmgemm_kernel<false,false>, cudaFuncAttributeMaxDynamicSharedMemorySize, MM_SMEM);
    cudaFuncSetAttribute(mmgemm_kernel<true,false>,  cudaFuncAttributeMaxDynamicSharedMemorySize, MM_SMEM);
    cudaFuncSetAttribute(mmgemm_kernel<true,true>,   cudaFuncAttributeMaxDynamicSharedMemorySize, MM_SMEM);

    const int rowsL = BATCH * LLAT;   // 1024
    const int rowsC = BATCH * NCTX;   // 32768

    // ---- weight convert + transpose (10 matrices) ----
    struct WDesc { const float* w; size_t off; int K, N; };
    const WDesc wd[10] = {
        {ca_wq,  WO_CAQ,  512,  512},  {ca_wkv, WO_CAKV, 512, 1024},
        {ca_wo,  WO_CAO,  512,  512},  {cf_w1,  WO_CF1,  512, 4096},
        {cf_w2,  WO_CF2,  2048, 512},  {sa_wq,  WO_SAQ,  512,  512},
        {sa_wkv, WO_SAKV, 512, 1024},  {sa_wo,  WO_SAO,  512,  512},
        {lf_w1,  WO_LF1,  512, 4096},  {lf_w2,  WO_LF2,  2048, 512},
    };
    for (int i = 0; i < 10; i++)
        wconv_kernel<<<dim3(wd[i].N / 32, wd[i].K / 32), dim3(32, 8)>>>(
            wd[i].w, whi + wd[i].off, wlo + wd[i].off, wd[i].K, wd[i].N);

    // ---- cross attention ----
    ln_bf16_kernel<<<rowsL, 128>>>(latents, ca_ln_w, ca_ln_b, xnh, xnl);
    ln_bf16_kernel<<<rowsC, 128>>>(context, ca_lnc_w, ca_lnc_b, cnh, cnl);
    mmgemm_kernel<false,false><<<dim3(4, 8),   256, MM_SMEM>>>(
        xnh, xnl, whi + WO_CAQ, wlo + WO_CAQ, nullptr, nullptr, qb, rowsL, 512, 512);
    mmgemm_kernel<false,false><<<dim3(8, 256), 256, MM_SMEM>>>(
        cnh, cnl, whi + WO_CAKV, wlo + WO_CAKV, nullptr, nullptr, kvb, rowsC, 1024, 512);
    flash_kernel<<<dim3(64, 2, 8), 128>>>(qb, kvb, pb, NCTX, 8);
    combine_bf16_kernel<<<8192, 64>>>(pb, aobh, aobl, 8);
    mmgemm_kernel<true,true><<<dim3(4, 8), 256, MM_SMEM>>>(
        aobh, aobl, whi + WO_CAO, wlo + WO_CAO, ca_bo, latents, x1, rowsL, 512, 512);

    // ---- cross FFN (GEGLU) ----
    ln_bf16_kernel<<<rowsL, 128>>>(x1, cf_ln_w, cf_ln_b, xnh, xnl);
    mmgemm_kernel<true,false><<<dim3(32, 8), 256, MM_SMEM>>>(
        xnh, xnl, whi + WO_CF1, wlo + WO_CF1, cf_b1, nullptr, hb, rowsL, 4096, 512);
    geglu_bf16_kernel<<<8192, 256>>>(hb, ggh, ggl);
    mmgemm_kernel<true,true><<<dim3(4, 8), 256, MM_SMEM>>>(
        ggh, ggl, whi + WO_CF2, wlo + WO_CF2, cf_b2, x1, x2, rowsL, 512, 2048);

    // ---- latent self-attention ----
    ln_bf16_kernel<<<rowsL, 128>>>(x2, sa_ln_w, sa_ln_b, xnh, xnl);
    mmgemm_kernel<false,false><<<dim3(4, 8), 256, MM_SMEM>>>(
        xnh, xnl, whi + WO_SAQ, wlo + WO_SAQ, nullptr, nullptr, qb, rowsL, 512, 512);
    mmgemm_kernel<false,false><<<dim3(8, 8), 256, MM_SMEM>>>(
        xnh, xnl, whi + WO_SAKV, wlo + WO_SAKV, nullptr, nullptr, kvb, rowsL, 1024, 512);
    flash_kernel<<<dim3(64, 2, 1), 128>>>(qb, kvb, pb, LLAT, 1);
    combine_bf16_kernel<<<8192, 64>>>(pb, aobh, aobl, 1);
    mmgemm_kernel<true,true><<<dim3(4, 8), 256, MM_SMEM>>>(
        aobh, aobl, whi + WO_SAO, wlo + WO_SAO, sa_bo, x2, x3, rowsL, 512, 512);

    // ---- latent FFN (GEGLU) ----
    ln_bf16_kernel<<<rowsL, 128>>>(x3, lf_ln_w, lf_ln_b, xnh, xnl);
    mmgemm_kernel<true,false><<<dim3(32, 8), 256, MM_SMEM>>>(
        xnh, xnl, whi + WO_LF1, wlo + WO_LF1, lf_b1, nullptr, hb, rowsL, 4096, 512);
    geglu_bf16_kernel<<<8192, 256>>>(hb, ggh, ggl);
    mmgemm_kernel<true,true><<<dim3(4, 8), 256, MM_SMEM>>>(
        ggh, ggl, whi + WO_LF2, wlo + WO_LF2, lf_b2, x3, (float*)d_out, rowsL, 512, 2048);
}

// round 4
// speedup vs baseline: 2.3399x; 1.4257x over previous
#include <cuda_runtime.h>
#include <cuda_fp16.h>
#include <math.h>
#include <stdint.h>

// ---------------------------------------------------------------------------
// Problem constants
// ---------------------------------------------------------------------------
#define DIM   512
#define NHEAD 8
#define DHEAD 64
#define BATCH 8
#define LLAT  128
#define NCTX  4096
#define FFD   2048
#define ATT_SCALE 0.125f

// ---------------------------------------------------------------------------
// Scratch (bytes, all offsets 1024-aligned)
// ---------------------------------------------------------------------------
#define SB_KVB   0ull            // f32 [32768,1024]  134217728
#define SB_HB    134217728ull    // f32 [1024,4096]    16777216
#define SB_PART  150994944ull    // f32 partials       17301504
#define SB_CNH   168296448ull    // f16 [32768,512]    33554432
#define SB_WH    201850880ull    // f16 packed transposed weights 16777216
#define SB_XNH   218628096ull    // f16 [1024,512]      1048576
#define SB_QB    219676672ull    // f32 [1024,512]      2097152
#define SB_AOBH  221773824ull    // f16 [1024,512]      1048576
#define SB_GGH   222822400ull    // f16 [1024,2048]     4194304
#define SB_X1    227016704ull    // f32 [1024,512]      2097152
#define SB_X2    229113856ull
#define SB_X3    231211008ull
#define SCRATCH_BYTES 233308160ull

__device__ __align__(1024) unsigned char g_scratch[SCRATCH_BYTES];

// Packed transposed-weight element offsets (f16 elements)
#define WO_CAQ   0ull
#define WO_CAKV  262144ull
#define WO_CAO   786432ull
#define WO_CF1   1048576ull
#define WO_CF2   3145728ull
#define WO_SAQ   4194304ull
#define WO_SAKV  4456448ull
#define WO_SAO   4980736ull
#define WO_LF1   5242880ull
#define WO_LF2   7340032ull

// ---------------------------------------------------------------------------
// Low-level helpers (baseline ISA: ldmatrix / mma.sync / cp.async)
// ---------------------------------------------------------------------------
__device__ __forceinline__ uint32_t smem_u32(const void* p) {
    uint32_t a;
    asm("{ .reg .u64 t; cvta.to.shared.u64 t, %1; cvt.u32.u64 %0, t; }" : "=r"(a) : "l"(p));
    return a;
}
__device__ __forceinline__ void cp16(uint32_t dst, const void* src) {
    asm volatile("cp.async.cg.shared.global [%0], [%1], 16;" :: "r"(dst), "l"(src) : "memory");
}
#define CP_COMMIT() asm volatile("cp.async.commit_group;" ::: "memory")
#define CP_WAIT(n)  asm volatile("cp.async.wait_group %0;" :: "n"(n) : "memory")

__device__ __forceinline__ void ldm_x4(uint32_t* r, uint32_t addr) {
    asm volatile("ldmatrix.sync.aligned.m8n8.x4.shared.b16 {%0,%1,%2,%3}, [%4];"
        : "=r"(r[0]), "=r"(r[1]), "=r"(r[2]), "=r"(r[3]) : "r"(addr));
}
__device__ __forceinline__ void mma16816(float* c, const uint32_t* a, uint32_t b0, uint32_t b1) {
    asm volatile("mma.sync.aligned.m16n8k16.row.col.f32.f16.f16.f32 "
        "{%0,%1,%2,%3}, {%4,%5,%6,%7}, {%8,%9}, {%0,%1,%2,%3};"
        : "+f"(c[0]), "+f"(c[1]), "+f"(c[2]), "+f"(c[3])
        : "r"(a[0]), "r"(a[1]), "r"(a[2]), "r"(a[3]), "r"(b0), "r"(b1));
}

// ---------------------------------------------------------------------------
// fp16 tensor-core GEMM: C[M,N] = A[M,K] @ B[N,K]^T (+bias)(+res)
// CTA 128x128, K-step 32, 8 warps (4m x 2n), warp tile 32x64,
// cp.async 3-stage pipeline, one __syncthreads per K-step.
// ---------------------------------------------------------------------------
#define ROW_ELEMS 40                       // 32 + 8 pad (f16)
#define OP_BYTES  (128 * ROW_ELEMS * 2)    // 10240
#define STAGE_BYTES (2 * OP_BYTES)         // 20480: A|B
#define MM_STAGES 3
#define MM_SMEM (MM_STAGES * STAGE_BYTES)  // 61440

__device__ __forceinline__ void mm_load_stage(
    uint32_t sbase, const __half* __restrict__ A, const __half* __restrict__ B,
    int bm, int bn, int K, int k0, int tid)
{
    #pragma unroll
    for (int o = 0; o < 2; o++) {
        const __half* base = o ? B : A;
        int g0 = o ? bn : bm;
        #pragma unroll
        for (int h = 0; h < 2; h++) {
            int idx = h * 256 + tid;          // 0..511 16B chunks
            int row = idx >> 2, c = idx & 3;
            cp16(sbase + o * OP_BYTES + row * (ROW_ELEMS * 2) + c * 16,
                 base + (size_t)(g0 + row) * K + k0 + c * 8);
        }
    }
}

__device__ __forceinline__ void mm_compute_stage(
    uint32_t sbase, float (&acc)[2][8][4], int wm, int wn, int lane)
{
    const uint32_t aA = sbase;
    const uint32_t aB = sbase + OP_BYTES;
    int arow = lane & 15;
    int acolg = lane >> 4;
    int brow = ((lane >> 4) << 3) + (lane & 7);
    int bcolg = (lane >> 3) & 1;
    #pragma unroll
    for (int kk = 0; kk < 2; kk++) {
        int k0 = kk * 16;
        uint32_t af[2][4];
        #pragma unroll
        for (int mb = 0; mb < 2; mb++) {
            uint32_t off = (uint32_t)((wm * 32 + mb * 16 + arow) * ROW_ELEMS + k0 + acolg * 8) * 2;
            ldm_x4(af[mb], aA + off);
        }
        uint32_t bfm[4][4];
        #pragma unroll
        for (int j = 0; j < 4; j++) {
            uint32_t off = (uint32_t)((wn * 64 + j * 16 + brow) * ROW_ELEMS + k0 + bcolg * 8) * 2;
            ldm_x4(bfm[j], aB + off);
        }
        #pragma unroll
        for (int mb = 0; mb < 2; mb++)
            #pragma unroll
            for (int j = 0; j < 4; j++)
                #pragma unroll
                for (int p = 0; p < 2; p++)
                    mma16816(acc[mb][j * 2 + p], af[mb], bfm[j][p * 2], bfm[j][p * 2 + 1]);
    }
}

template<bool BIAS, bool RES>
__global__ __launch_bounds__(256) void mmgemm_kernel(
    const __half* __restrict__ A, const __half* __restrict__ B,
    const float* __restrict__ bias, const float* __restrict__ res,
    float* __restrict__ C, int M, int N, int K)
{
    extern __shared__ __align__(128) char smem[];
    uint32_t sb = smem_u32(smem);
    int tid = threadIdx.x;
    int wid = tid >> 5, lane = tid & 31;
    int wm = wid >> 1, wn = wid & 1;
    int bm = blockIdx.y * 128, bn = blockIdx.x * 128;

    float acc[2][8][4];
    #pragma unroll
    for (int a = 0; a < 2; a++)
        #pragma unroll
        for (int b = 0; b < 8; b++)
            #pragma unroll
            for (int c = 0; c < 4; c++) acc[a][b][c] = 0.0f;

    const int NC = K >> 5;
    // preload stages 0,1
    mm_load_stage(sb, A, B, bm, bn, K, 0, tid);
    CP_COMMIT();
    if (NC > 1) {
        mm_load_stage(sb + STAGE_BYTES, A, B, bm, bn, K, 32, tid);
        CP_COMMIT();
    }
    for (int c = 0; c < NC; c++) {
        if (c + 2 < NC) CP_WAIT(1); else CP_WAIT(0);
        __syncthreads();
        if (c + 2 < NC) {
            mm_load_stage(sb + ((c + 2) % MM_STAGES) * STAGE_BYTES, A, B, bm, bn, K, (c + 2) << 5, tid);
            CP_COMMIT();
        }
        mm_compute_stage(sb + (c % MM_STAGES) * STAGE_BYTES, acc, wm, wn, lane);
    }

    // epilogue
    int lane4 = lane >> 2;
    int lane2 = (lane & 3) << 1;
    #pragma unroll
    for (int mb = 0; mb < 2; mb++) {
        int r0 = bm + wm * 32 + mb * 16 + lane4;
        #pragma unroll
        for (int nb = 0; nb < 8; nb++) {
            int cc = bn + wn * 64 + nb * 8 + lane2;
            float* a = acc[mb][nb];
            float2 v0 = make_float2(a[0], a[1]);
            float2 v1 = make_float2(a[2], a[3]);
            if (BIAS) {
                float2 bb = *reinterpret_cast<const float2*>(bias + cc);
                v0.x += bb.x; v0.y += bb.y; v1.x += bb.x; v1.y += bb.y;
            }
            size_t o0 = (size_t)r0 * N + cc;
            size_t o1 = (size_t)(r0 + 8) * N + cc;
            if (RES) {
                float2 rr = *reinterpret_cast<const float2*>(res + o0);
                v0.x += rr.x; v0.y += rr.y;
                rr = *reinterpret_cast<const float2*>(res + o1);
                v1.x += rr.x; v1.y += rr.y;
            }
            *reinterpret_cast<float2*>(C + o0) = v0;
            *reinterpret_cast<float2*>(C + o1) = v1;
        }
    }
}

// ---------------------------------------------------------------------------
// LayerNorm (last dim 512) -> fp16
// ---------------------------------------------------------------------------
__global__ __launch_bounds__(128) void ln_f16_kernel(
    const float* __restrict__ x, const float* __restrict__ w,
    const float* __restrict__ b, __half* __restrict__ out)
{
    int row = blockIdx.x;
    int t = threadIdx.x;
    float4 v = reinterpret_cast<const float4*>(x + (size_t)row * DIM)[t];
    float s  = v.x + v.y + v.z + v.w;
    float ss = v.x*v.x + v.y*v.y + v.z*v.z + v.w*v.w;
    #pragma unroll
    for (int o = 16; o > 0; o >>= 1) {
        s  += __shfl_xor_sync(0xffffffffu, s,  o);
        ss += __shfl_xor_sync(0xffffffffu, ss, o);
    }
    __shared__ float rs[4], rss[4];
    int warp = t >> 5;
    if ((t & 31) == 0) { rs[warp] = s; rss[warp] = ss; }
    __syncthreads();
    s  = rs[0] + rs[1] + rs[2] + rs[3];
    ss = rss[0] + rss[1] + rss[2] + rss[3];
    float mu  = s * (1.0f / DIM);
    float var = ss * (1.0f / DIM) - mu * mu;
    float inv = rsqrtf(var + 1e-5f);
    float4 wv = reinterpret_cast<const float4*>(w)[t];
    float4 bv = reinterpret_cast<const float4*>(b)[t];
    __half2 h0 = __floats2half2_rn((v.x - mu) * inv * wv.x + bv.x,
                                   (v.y - mu) * inv * wv.y + bv.y);
    __half2 h1 = __floats2half2_rn((v.z - mu) * inv * wv.z + bv.z,
                                   (v.w - mu) * inv * wv.w + bv.w);
    __half2* op = reinterpret_cast<__half2*>(out + (size_t)row * DIM + t * 4);
    op[0] = h0; op[1] = h1;
}

// ---------------------------------------------------------------------------
// Weight convert + transpose: W[K,N] f32 -> f16 [N,K]
// ---------------------------------------------------------------------------
__global__ __launch_bounds__(256) void wconv_kernel(
    const float* __restrict__ W, __half* __restrict__ out, int K, int N)
{
    __shared__ float tile[32][33];
    int tx = threadIdx.x, ty = threadIdx.y;
    int x = blockIdx.x * 32 + tx;
    int y0 = blockIdx.y * 32;
    #pragma unroll
    for (int j = ty; j < 32; j += 8)
        tile[j][tx] = W[(size_t)(y0 + j) * N + x];
    __syncthreads();
    #pragma unroll
    for (int j = ty; j < 32; j += 8) {
        int n = blockIdx.x * 32 + j;
        int k = y0 + tx;
        out[(size_t)n * K + k] = __float2half(tile[tx][j]);
    }
}

// ---------------------------------------------------------------------------
// Flash attention (fp32, split-KV)
// ---------------------------------------------------------------------------
__global__ __launch_bounds__(128) void flash_kernel(
    const float* __restrict__ Q, const float* __restrict__ KV,
    float* __restrict__ part, int Nk, int nsplit)
{
    const int TJ = 32;
    __shared__ float Ks[TJ][DHEAD];
    __shared__ float Vs[TJ][DHEAD];

    int bh = blockIdx.x;
    int b = bh >> 3, h = bh & 7;
    int r0 = blockIdx.y * 64;
    int split = blockIdx.z;
    int chunk = Nk / nsplit;
    int j0 = split * chunk;
    int t = threadIdx.x;
    int row = r0 + (t >> 1);
    int half = t & 1;

    const float* qp = Q + ((size_t)(b * LLAT + row)) * DIM + h * DHEAD + half * 32;
    float qr[32];
    #pragma unroll
    for (int c = 0; c < 8; c++) {
        float4 q4 = reinterpret_cast<const float4*>(qp)[c];
        qr[c*4+0] = q4.x; qr[c*4+1] = q4.y; qr[c*4+2] = q4.z; qr[c*4+3] = q4.w;
    }
    float acc[32];
    #pragma unroll
    for (int c = 0; c < 32; c++) acc[c] = 0.0f;
    float m = -INFINITY, l = 0.0f;

    const float* kvbase = KV + (size_t)b * Nk * (2 * DIM);

    for (int jt = 0; jt < chunk; jt += TJ) {
        __syncthreads();
        #pragma unroll
        for (int i = 0; i < 4; i++) {
            int f  = i * 128 + t;
            int j  = f >> 4;
            int c4 = f & 15;
            const float* src = kvbase + (size_t)(j0 + jt + j) * (2 * DIM) + h * DHEAD + c4 * 4;
            float4 kk = *reinterpret_cast<const float4*>(src);
            float4 vv = *reinterpret_cast<const float4*>(src + DIM);
            *reinterpret_cast<float4*>(&Ks[j][c4 * 4]) = kk;
            *reinterpret_cast<float4*>(&Vs[j][c4 * 4]) = vv;
        }
        __syncthreads();
        #pragma unroll 2
        for (int j = 0; j < TJ; j++) {
            float s = 0.0f;
            const float4* kp = reinterpret_cast<const float4*>(&Ks[j][half * 32]);
            #pragma unroll
            for (int c = 0; c < 8; c++) {
                float4 kk = kp[c];
                s += qr[c*4+0]*kk.x + qr[c*4+1]*kk.y + qr[c*4+2]*kk.z + qr[c*4+3]*kk.w;
            }
            s += __shfl_xor_sync(0xffffffffu, s, 1);
            s *= ATT_SCALE;
            float mold = m;
            m = fmaxf(m, s);
            float corr = __expf(mold - m);
            float p    = __expf(s - m);
            l = l * corr + p;
            const float4* vp = reinterpret_cast<const float4*>(&Vs[j][half * 32]);
            #pragma unroll
            for (int c = 0; c < 8; c++) {
                float4 vv = vp[c];
                acc[c*4+0] = acc[c*4+0]*corr + p*vv.x;
                acc[c*4+1] = acc[c*4+1]*corr + p*vv.y;
                acc[c*4+2] = acc[c*4+2]*corr + p*vv.z;
                acc[c*4+3] = acc[c*4+3]*corr + p*vv.w;
            }
        }
    }

    size_t base = ((((size_t)(b * NHEAD + h) * LLAT + row) * nsplit) + split) * 66;
    if (half == 0) { part[base] = m; part[base + 1] = l; }
    #pragma unroll
    for (int c = 0; c < 32; c++) part[base + 2 + half * 32 + c] = acc[c];
}

// ---------------------------------------------------------------------------
// Combine split-KV partials -> fp16 attention output
// ---------------------------------------------------------------------------
__global__ __launch_bounds__(64) void combine_f16_kernel(
    const float* __restrict__ part, __half* __restrict__ out, int nsplit)
{
    int idx = blockIdx.x;
    int i  = idx & (LLAT - 1);
    int bh = idx >> 7;
    int b = bh >> 3, h = bh & 7;
    int d = threadIdx.x;
    size_t base = (size_t)idx * nsplit * 66;
    float M = -INFINITY;
    for (int s = 0; s < nsplit; s++) M = fmaxf(M, part[base + (size_t)s * 66]);
    float L = 0.0f, o = 0.0f;
    for (int s = 0; s < nsplit; s++) {
        float a = __expf(part[base + (size_t)s * 66] - M);
        L += a * part[base + (size_t)s * 66 + 1];
        o += a * part[base + (size_t)s * 66 + 2 + d];
    }
    out[((size_t)(b * LLAT + i)) * DIM + h * DHEAD + d] = __float2half(o / L);
}

// ---------------------------------------------------------------------------
// GEGLU (exact erf) -> fp16
// ---------------------------------------------------------------------------
__global__ __launch_bounds__(256) void geglu_f16_kernel(
    const float* __restrict__ hbuf, __half* __restrict__ out)
{
    int idx = blockIdx.x * blockDim.x + threadIdx.x;
    int row = idx >> 11;
    int c   = idx & 2047;
    float a = hbuf[(size_t)row * (2 * FFD) + c];
    float g = hbuf[(size_t)row * (2 * FFD) + FFD + c];
    float y = a * (0.5f * g * (1.0f + erff(g * 0.70710678118654752f)));
    out[idx] = __float2half(y);
}

// ---------------------------------------------------------------------------
// Host orchestration
// ---------------------------------------------------------------------------
extern "C" void kernel_launch(void* const* d_in, const int* in_sizes, int n_in,
                              void* d_out, int out_size)
{
    (void)in_sizes; (void)n_in; (void)out_size;
    const float* context = (const float*)d_in[0];
    const float* latents = (const float*)d_in[1];
    const float* ca_ln_w  = (const float*)d_in[2];
    const float* ca_ln_b  = (const float*)d_in[3];
    const float* ca_lnc_w = (const float*)d_in[4];
    const float* ca_lnc_b = (const float*)d_in[5];
    const float* ca_wq  = (const float*)d_in[6];
    const float* ca_wkv = (const float*)d_in[7];
    const float* ca_wo  = (const float*)d_in[8];
    const float* ca_bo  = (const float*)d_in[9];
    const float* cf_ln_w = (const float*)d_in[10];
    const float* cf_ln_b = (const float*)d_in[11];
    const float* cf_w1 = (const float*)d_in[12];
    const float* cf_b1 = (const float*)d_in[13];
    const float* cf_w2 = (const float*)d_in[14];
    const float* cf_b2 = (const float*)d_in[15];
    const float* sa_ln_w = (const float*)d_in[16];
    const float* sa_ln_b = (const float*)d_in[17];
    const float* sa_wq  = (const float*)d_in[18];
    const float* sa_wkv = (const float*)d_in[19];
    const float* sa_wo  = (const float*)d_in[20];
    const float* sa_bo  = (const float*)d_in[21];
    const float* lf_ln_w = (const float*)d_in[22];
    const float* lf_ln_b = (const float*)d_in[23];
    const float* lf_w1 = (const float*)d_in[24];
    const float* lf_b1 = (const float*)d_in[25];
    const float* lf_w2 = (const float*)d_in[26];
    const float* lf_b2 = (const float*)d_in[27];

    void* sp = nullptr;
    cudaGetSymbolAddress(&sp, g_scratch);
    unsigned char* S = (unsigned char*)sp;
    float* kvb  = (float*)(S + SB_KVB);
    float* hb   = (float*)(S + SB_HB);
    float* pb   = (float*)(S + SB_PART);
    __half* cnh = (__half*)(S + SB_CNH);
    __half* wh  = (__half*)(S + SB_WH);
    __half* xnh = (__half*)(S + SB_XNH);
    float* qb   = (float*)(S + SB_QB);
    __half* aobh= (__half*)(S + SB_AOBH);
    __half* ggh = (__half*)(S + SB_GGH);
    float* x1   = (float*)(S + SB_X1);
    float* x2   = (float*)(S + SB_X2);
    float* x3   = (float*)(S + SB_X3);

    cudaFuncSetAttribute(mmgemm_kernel<false,false>, cudaFuncAttributeMaxDynamicSharedMemorySize, MM_SMEM);
    cudaFuncSetAttribute(mmgemm_kernel<true,false>,  cudaFuncAttributeMaxDynamicSharedMemorySize, MM_SMEM);
    cudaFuncSetAttribute(mmgemm_kernel<true,true>,   cudaFuncAttributeMaxDynamicSharedMemorySize, MM_SMEM);

    const int rowsL = BATCH * LLAT;   // 1024
    const int rowsC = BATCH * NCTX;   // 32768

    // ---- weight convert + transpose (10 matrices) ----
    struct WDesc { const float* w; size_t off; int K, N; };
    const WDesc wd[10] = {
        {ca_wq,  WO_CAQ,  512,  512},  {ca_wkv, WO_CAKV, 512, 1024},
        {ca_wo,  WO_CAO,  512,  512},  {cf_w1,  WO_CF1,  512, 4096},
        {cf_w2,  WO_CF2,  2048, 512},  {sa_wq,  WO_SAQ,  512,  512},
        {sa_wkv, WO_SAKV, 512, 1024},  {sa_wo,  WO_SAO,  512,  512},
        {lf_w1,  WO_LF1,  512, 4096},  {lf_w2,  WO_LF2,  2048, 512},
    };
    for (int i = 0; i < 10; i++)
        wconv_kernel<<<dim3(wd[i].N / 32, wd[i].K / 32), dim3(32, 8)>>>(
            wd[i].w, wh + wd[i].off, wd[i].K, wd[i].N);

    // ---- cross attention ----
    ln_f16_kernel<<<rowsL, 128>>>(latents, ca_ln_w, ca_ln_b, xnh);
    ln_f16_kernel<<<rowsC, 128>>>(context, ca_lnc_w, ca_lnc_b, cnh);
    mmgemm_kernel<false,false><<<dim3(4, 8),   256, MM_SMEM>>>(
        xnh, wh + WO_CAQ, nullptr, nullptr, qb, rowsL, 512, 512);
    mmgemm_kernel<false,false><<<dim3(8, 256), 256, MM_SMEM>>>(
        cnh, wh + WO_CAKV, nullptr, nullptr, kvb, rowsC, 1024, 512);
    flash_kernel<<<dim3(64, 2, 8), 128>>>(qb, kvb, pb, NCTX, 8);
    combine_f16_kernel<<<8192, 64>>>(pb, aobh, 8);
    mmgemm_kernel<true,true><<<dim3(4, 8), 256, MM_SMEM>>>(
        aobh, wh + WO_CAO, ca_bo, latents, x1, rowsL, 512, 512);

    // ---- cross FFN (GEGLU) ----
    ln_f16_kernel<<<rowsL, 128>>>(x1, cf_ln_w, cf_ln_b, xnh);
    mmgemm_kernel<true,false><<<dim3(32, 8), 256, MM_SMEM>>>(
        xnh, wh + WO_CF1, cf_b1, nullptr, hb, rowsL, 4096, 512);
    geglu_f16_kernel<<<8192, 256>>>(hb, ggh);
    mmgemm_kernel<true,true><<<dim3(4, 8), 256, MM_SMEM>>>(
        ggh, wh + WO_CF2, cf_b2, x1, x2, rowsL, 512, 2048);

    // ---- latent self-attention ----
    ln_f16_kernel<<<rowsL, 128>>>(x2, sa_ln_w, sa_ln_b, xnh);
    mmgemm_kernel<false,false><<<dim3(4, 8), 256, MM_SMEM>>>(
        xnh, wh + WO_SAQ, nullptr, nullptr, qb, rowsL, 512, 512);
    mmgemm_kernel<false,false><<<dim3(8, 8), 256, MM_SMEM>>>(
        xnh, wh + WO_SAKV, nullptr, nullptr, kvb, rowsL, 1024, 512);
    flash_kernel<<<dim3(64, 2, 1), 128>>>(qb, kvb, pb, LLAT, 1);
    combine_f16_kernel<<<8192, 64>>>(pb, aobh, 1);
    mmgemm_kernel<true,true><<<dim3(4, 8), 256, MM_SMEM>>>(
        aobh, wh + WO_SAO, sa_bo, x2, x3, rowsL, 512, 512);

    // ---- latent FFN (GEGLU) ----
    ln_f16_kernel<<<rowsL, 128>>>(x3, lf_ln_w, lf_ln_b, xnh);
    mmgemm_kernel<true,false><<<dim3(32, 8), 256, MM_SMEM>>>(
        xnh, wh + WO_LF1, lf_b1, nullptr, hb, rowsL, 4096, 512);
    geglu_f16_kernel<<<8192, 256>>>(hb, ggh);
    mmgemm_kernel<true,true><<<dim3(4, 8), 256, MM_SMEM>>>(
        ggh, wh + WO_LF2, lf_b2, x3, (float*)d_out, rowsL, 512, 2048);
}

// round 5
// speedup vs baseline: 4.6344x; 1.9806x over previous
#include <cuda_runtime.h>
#include <cuda_fp16.h>
#include <math.h>
#include <stdint.h>

// ---------------------------------------------------------------------------
// Problem constants
// ---------------------------------------------------------------------------
#define DIM   512
#define NHEAD 8
#define DHEAD 64
#define BATCH 8
#define LLAT  128
#define NCTX  4096
#define FFD   2048
#define ATT_SCALE 0.125f
#define LOG2E 1.44269504f

// ---------------------------------------------------------------------------
// Scratch (bytes, all offsets 1024-aligned)
// ---------------------------------------------------------------------------
#define SB_KVB   0ull            // f16 [32768,1024]   67108864
#define SB_HB    134217728ull    // f16 [1024,4096]     8388608
#define SB_PART  150994944ull    // f32 partials       17301504
#define SB_CNH   168296448ull    // f16 [32768,512]    33554432
#define SB_WH    201850880ull    // f16 packed transposed weights 16777216
#define SB_XNH   218628096ull    // f16 [1024,512]      1048576
#define SB_QB    219676672ull    // f16 [1024,512]      1048576
#define SB_AOBH  221773824ull    // f16 [1024,512]      1048576
#define SB_GGH   222822400ull    // f16 [1024,2048]     4194304
#define SB_X1    227016704ull    // f32 [1024,512]      2097152
#define SB_X2    229113856ull
#define SB_X3    231211008ull
#define SCRATCH_BYTES 233308160ull

__device__ __align__(1024) unsigned char g_scratch[SCRATCH_BYTES];

// Packed transposed-weight element offsets (f16 elements)
#define WO_CAQ   0ull
#define WO_CAKV  262144ull
#define WO_CAO   786432ull
#define WO_CF1   1048576ull
#define WO_CF2   3145728ull
#define WO_SAQ   4194304ull
#define WO_SAKV  4456448ull
#define WO_SAO   4980736ull
#define WO_LF1   5242880ull
#define WO_LF2   7340032ull

// ---------------------------------------------------------------------------
// Low-level helpers
// ---------------------------------------------------------------------------
__device__ __forceinline__ uint32_t smem_u32(const void* p) {
    uint32_t a;
    asm("{ .reg .u64 t; cvta.to.shared.u64 t, %1; cvt.u32.u64 %0, t; }" : "=r"(a) : "l"(p));
    return a;
}
__device__ __forceinline__ void cp16(uint32_t dst, const void* src) {
    asm volatile("cp.async.cg.shared.global [%0], [%1], 16;" :: "r"(dst), "l"(src) : "memory");
}
#define CP_COMMIT() asm volatile("cp.async.commit_group;" ::: "memory")
#define CP_WAIT(n)  asm volatile("cp.async.wait_group %0;" :: "n"(n) : "memory")

__device__ __forceinline__ void ldm_x4(uint32_t* r, uint32_t addr) {
    asm volatile("ldmatrix.sync.aligned.m8n8.x4.shared.b16 {%0,%1,%2,%3}, [%4];"
        : "=r"(r[0]), "=r"(r[1]), "=r"(r[2]), "=r"(r[3]) : "r"(addr));
}
__device__ __forceinline__ void ldm_x4_t(uint32_t* r, uint32_t addr) {
    asm volatile("ldmatrix.sync.aligned.m8n8.x4.trans.shared.b16 {%0,%1,%2,%3}, [%4];"
        : "=r"(r[0]), "=r"(r[1]), "=r"(r[2]), "=r"(r[3]) : "r"(addr));
}
__device__ __forceinline__ void mma16816(float* c, const uint32_t* a, uint32_t b0, uint32_t b1) {
    asm volatile("mma.sync.aligned.m16n8k16.row.col.f32.f16.f16.f32 "
        "{%0,%1,%2,%3}, {%4,%5,%6,%7}, {%8,%9}, {%0,%1,%2,%3};"
        : "+f"(c[0]), "+f"(c[1]), "+f"(c[2]), "+f"(c[3])
        : "r"(a[0]), "r"(a[1]), "r"(a[2]), "r"(a[3]), "r"(b0), "r"(b1));
}
__device__ __forceinline__ float ex2(float x) {
    float y; asm("ex2.approx.f32 %0, %1;" : "=f"(y) : "f"(x)); return y;
}
__device__ __forceinline__ uint32_t packh2(float a, float b) {
    __half2 h = __floats2half2_rn(a, b);
    return *reinterpret_cast<uint32_t*>(&h);
}
__device__ __forceinline__ void store2(float* p, float2 v) {
    *reinterpret_cast<float2*>(p) = v;
}
__device__ __forceinline__ void store2(__half* p, float2 v) {
    *reinterpret_cast<__half2*>(p) = __floats2half2_rn(v.x, v.y);
}

// ---------------------------------------------------------------------------
// fp16 tensor-core GEMM: C[M,N] = A[M,K] @ B[N,K]^T (+bias)(+res)
// CTA 128x128, K-step 32, 8 warps (4m x 2n), 3-stage cp.async pipeline.
// ---------------------------------------------------------------------------
#define ROW_ELEMS 40
#define OP_BYTES  (128 * ROW_ELEMS * 2)
#define STAGE_BYTES (2 * OP_BYTES)
#define MM_STAGES 3
#define MM_SMEM (MM_STAGES * STAGE_BYTES)

__device__ __forceinline__ void mm_load_stage(
    uint32_t sbase, const __half* __restrict__ A, const __half* __restrict__ B,
    int bm, int bn, int K, int k0, int tid)
{
    #pragma unroll
    for (int o = 0; o < 2; o++) {
        const __half* base = o ? B : A;
        int g0 = o ? bn : bm;
        #pragma unroll
        for (int h = 0; h < 2; h++) {
            int idx = h * 256 + tid;
            int row = idx >> 2, c = idx & 3;
            cp16(sbase + o * OP_BYTES + row * (ROW_ELEMS * 2) + c * 16,
                 base + (size_t)(g0 + row) * K + k0 + c * 8);
        }
    }
}

__device__ __forceinline__ void mm_compute_stage(
    uint32_t sbase, float (&acc)[2][8][4], int wm, int wn, int lane)
{
    const uint32_t aA = sbase;
    const uint32_t aB = sbase + OP_BYTES;
    int arow = lane & 15;
    int acolg = lane >> 4;
    int brow = ((lane >> 4) << 3) + (lane & 7);
    int bcolg = (lane >> 3) & 1;
    #pragma unroll
    for (int kk = 0; kk < 2; kk++) {
        int k0 = kk * 16;
        uint32_t af[2][4];
        #pragma unroll
        for (int mb = 0; mb < 2; mb++) {
            uint32_t off = (uint32_t)((wm * 32 + mb * 16 + arow) * ROW_ELEMS + k0 + acolg * 8) * 2;
            ldm_x4(af[mb], aA + off);
        }
        uint32_t bfm[4][4];
        #pragma unroll
        for (int j = 0; j < 4; j++) {
            uint32_t off = (uint32_t)((wn * 64 + j * 16 + brow) * ROW_ELEMS + k0 + bcolg * 8) * 2;
            ldm_x4(bfm[j], aB + off);
        }
        #pragma unroll
        for (int mb = 0; mb < 2; mb++)
            #pragma unroll
            for (int j = 0; j < 4; j++)
                #pragma unroll
                for (int p = 0; p < 2; p++)
                    mma16816(acc[mb][j * 2 + p], af[mb], bfm[j][p * 2], bfm[j][p * 2 + 1]);
    }
}

template<bool BIAS, bool RES, typename OutT>
__global__ __launch_bounds__(256) void mmgemm_kernel(
    const __half* __restrict__ A, const __half* __restrict__ B,
    const float* __restrict__ bias, const float* __restrict__ res,
    OutT* __restrict__ C, int M, int N, int K)
{
    extern __shared__ __align__(128) char smem[];
    uint32_t sb = smem_u32(smem);
    int tid = threadIdx.x;
    int wid = tid >> 5, lane = tid & 31;
    int wm = wid >> 1, wn = wid & 1;
    int bm = blockIdx.y * 128, bn = blockIdx.x * 128;

    float acc[2][8][4];
    #pragma unroll
    for (int a = 0; a < 2; a++)
        #pragma unroll
        for (int b = 0; b < 8; b++)
            #pragma unroll
            for (int c = 0; c < 4; c++) acc[a][b][c] = 0.0f;

    const int NC = K >> 5;
    mm_load_stage(sb, A, B, bm, bn, K, 0, tid);
    CP_COMMIT();
    if (NC > 1) {
        mm_load_stage(sb + STAGE_BYTES, A, B, bm, bn, K, 32, tid);
        CP_COMMIT();
    }
    for (int c = 0; c < NC; c++) {
        if (c + 2 < NC) CP_WAIT(1); else CP_WAIT(0);
        __syncthreads();
        if (c + 2 < NC) {
            mm_load_stage(sb + ((c + 2) % MM_STAGES) * STAGE_BYTES, A, B, bm, bn, K, (c + 2) << 5, tid);
            CP_COMMIT();
        }
        mm_compute_stage(sb + (c % MM_STAGES) * STAGE_BYTES, acc, wm, wn, lane);
    }

    int lane4 = lane >> 2;
    int lane2 = (lane & 3) << 1;
    #pragma unroll
    for (int mb = 0; mb < 2; mb++) {
        int r0 = bm + wm * 32 + mb * 16 + lane4;
        #pragma unroll
        for (int nb = 0; nb < 8; nb++) {
            int cc = bn + wn * 64 + nb * 8 + lane2;
            float* a = acc[mb][nb];
            float2 v0 = make_float2(a[0], a[1]);
            float2 v1 = make_float2(a[2], a[3]);
            if (BIAS) {
                float2 bb = *reinterpret_cast<const float2*>(bias + cc);
                v0.x += bb.x; v0.y += bb.y; v1.x += bb.x; v1.y += bb.y;
            }
            size_t o0 = (size_t)r0 * N + cc;
            size_t o1 = (size_t)(r0 + 8) * N + cc;
            if (RES) {
                float2 rr = *reinterpret_cast<const float2*>(res + o0);
                v0.x += rr.x; v0.y += rr.y;
                rr = *reinterpret_cast<const float2*>(res + o1);
                v1.x += rr.x; v1.y += rr.y;
            }
            store2(C + o0, v0);
            store2(C + o1, v1);
        }
    }
}

// ---------------------------------------------------------------------------
// Tensor-core flash attention (fp16 QKV, fp32 online softmax, split-KV)
// grid (B*H, nsplit), 256 threads = 8 warps x 16 query rows.
// SMEM: Q[128][72] + 2 stages of (K[64][72], V[64][72])
// ---------------------------------------------------------------------------
#define FPAD 72
#define FQ_BYTES   (128 * FPAD * 2)        // 18432
#define FKV_BYTES  (64 * FPAD * 2)         // 9216
#define FSTAGE     (2 * FKV_BYTES)         // 18432
#define FLASH_SMEM (FQ_BYTES + 2 * FSTAGE) // 55296

__device__ __forceinline__ void flash_load_tile(
    uint32_t stage, const __half* __restrict__ kvbase, int key0, int tid)
{
    #pragma unroll
    for (int i = 0; i < 4; i++) {
        int idx = i * 256 + tid;         // 0..1023
        int o = idx >> 9;                // 0 = K, 1 = V
        int key = (idx >> 3) & 63;
        int c = idx & 7;
        cp16(stage + o * FKV_BYTES + (key * FPAD + c * 8) * 2,
             kvbase + (size_t)(key0 + key) * (2 * DIM) + o * DIM + c * 8);
    }
}

__global__ __launch_bounds__(256) void flash_tc_kernel(
    const __half* __restrict__ Q, const __half* __restrict__ KV,
    float* __restrict__ part, int Nk, int nsplit)
{
    extern __shared__ __align__(128) char fsm[];
    uint32_t sb = smem_u32(fsm);
    const uint32_t Qs = sb;

    int bh = blockIdx.x;
    int b = bh >> 3, h = bh & 7;
    int split = blockIdx.y;
    int chunk = Nk / nsplit;
    int j0 = split * chunk;
    int ntiles = chunk >> 6;
    int tid = threadIdx.x, w = tid >> 5, lane = tid & 31;

    const __half* qbase  = Q  + (size_t)(b * LLAT) * DIM + h * DHEAD;
    const __half* kvbase = KV + (size_t)b * Nk * (2 * DIM) + h * DHEAD;

    // load Q tile (128 rows x 64 halves)
    #pragma unroll
    for (int i = 0; i < 4; i++) {
        int idx = i * 256 + tid;
        int row = idx >> 3, c = idx & 7;
        cp16(Qs + (row * FPAD + c * 8) * 2, qbase + (size_t)row * DIM + c * 8);
    }
    flash_load_tile(sb + FQ_BYTES, kvbase, j0, tid);
    CP_COMMIT();

    float O[8][4];
    #pragma unroll
    for (int j = 0; j < 8; j++)
        #pragma unroll
        for (int r = 0; r < 4; r++) O[j][r] = 0.0f;
    uint32_t qf[4][4];
    float m0 = -INFINITY, m1 = -INFINITY, l0 = 0.0f, l1 = 0.0f;

    int arow = lane & 15, acolg = lane >> 4;
    int brow = ((lane >> 4) << 3) + (lane & 7), bcolg = (lane >> 3) & 1;
    int krow = (((lane >> 3) & 1) << 3) + (lane & 7), ncolg = lane >> 4;
    const float k2 = ATT_SCALE * LOG2E;

    for (int t = 0; t < ntiles; t++) {
        if (t + 1 < ntiles) {
            flash_load_tile(sb + FQ_BYTES + ((t + 1) & 1) * FSTAGE, kvbase, j0 + (t + 1) * 64, tid);
            CP_COMMIT();
            CP_WAIT(1);
        } else {
            CP_WAIT(0);
        }
        __syncthreads();
        if (t == 0) {
            #pragma unroll
            for (int kk = 0; kk < 4; kk++)
                ldm_x4(qf[kk], Qs + ((w * 16 + arow) * FPAD + kk * 16 + acolg * 8) * 2);
        }
        uint32_t Kt = sb + FQ_BYTES + (t & 1) * FSTAGE;
        uint32_t Vt = Kt + FKV_BYTES;

        // S = Q @ K^T (raw scores)
        float S[8][4];
        #pragma unroll
        for (int j = 0; j < 8; j++)
            #pragma unroll
            for (int r = 0; r < 4; r++) S[j][r] = 0.0f;
        #pragma unroll
        for (int kk = 0; kk < 4; kk++) {
            #pragma unroll
            for (int jj = 0; jj < 4; jj++) {
                uint32_t bk[4];
                ldm_x4(bk, Kt + ((jj * 16 + brow) * FPAD + kk * 16 + bcolg * 8) * 2);
                mma16816(S[jj * 2],     qf[kk], bk[0], bk[1]);
                mma16816(S[jj * 2 + 1], qf[kk], bk[2], bk[3]);
            }
        }

        // online softmax (row = lane>>2 for regs 0,1; row+8 for regs 2,3)
        float t0 = -INFINITY, t1 = -INFINITY;
        #pragma unroll
        for (int j = 0; j < 8; j++) {
            t0 = fmaxf(t0, fmaxf(S[j][0], S[j][1]));
            t1 = fmaxf(t1, fmaxf(S[j][2], S[j][3]));
        }
        #pragma unroll
        for (int o = 1; o < 4; o <<= 1) {
            t0 = fmaxf(t0, __shfl_xor_sync(0xffffffffu, t0, o));
            t1 = fmaxf(t1, __shfl_xor_sync(0xffffffffu, t1, o));
        }
        float m0n = fmaxf(m0, t0 * ATT_SCALE);
        float m1n = fmaxf(m1, t1 * ATT_SCALE);
        float corr0 = ex2((m0 - m0n) * LOG2E);
        float corr1 = ex2((m1 - m1n) * LOG2E);
        l0 *= corr0; l1 *= corr1;
        #pragma unroll
        for (int j = 0; j < 8; j++) {
            O[j][0] *= corr0; O[j][1] *= corr0;
            O[j][2] *= corr1; O[j][3] *= corr1;
        }
        float mb0 = m0n * LOG2E, mb1 = m1n * LOG2E;
        float ps0 = 0.0f, ps1 = 0.0f;
        uint32_t ph[4][4];
        #pragma unroll
        for (int kk2 = 0; kk2 < 4; kk2++) {
            int ja = 2 * kk2, jb = ja + 1;
            float pa0 = ex2(fmaf(S[ja][0], k2, -mb0));
            float pa1 = ex2(fmaf(S[ja][1], k2, -mb0));
            float pa2 = ex2(fmaf(S[ja][2], k2, -mb1));
            float pa3 = ex2(fmaf(S[ja][3], k2, -mb1));
            float pb0 = ex2(fmaf(S[jb][0], k2, -mb0));
            float pb1 = ex2(fmaf(S[jb][1], k2, -mb0));
            float pb2 = ex2(fmaf(S[jb][2], k2, -mb1));
            float pb3 = ex2(fmaf(S[jb][3], k2, -mb1));
            ps0 += pa0 + pa1 + pb0 + pb1;
            ps1 += pa2 + pa3 + pb2 + pb3;
            ph[kk2][0] = packh2(pa0, pa1);
            ph[kk2][1] = packh2(pa2, pa3);
            ph[kk2][2] = packh2(pb0, pb1);
            ph[kk2][3] = packh2(pb2, pb3);
        }
        #pragma unroll
        for (int o = 1; o < 4; o <<= 1) {
            ps0 += __shfl_xor_sync(0xffffffffu, ps0, o);
            ps1 += __shfl_xor_sync(0xffffffffu, ps1, o);
        }
        l0 += ps0; l1 += ps1;
        m0 = m0n; m1 = m1n;

        // O += P @ V  (V via trans ldmatrix)
        #pragma unroll
        for (int kk2 = 0; kk2 < 4; kk2++) {
            #pragma unroll
            for (int jj = 0; jj < 4; jj++) {
                uint32_t bv[4];
                ldm_x4_t(bv, Vt + ((kk2 * 16 + krow) * FPAD + jj * 16 + ncolg * 8) * 2);
                mma16816(O[jj * 2],     ph[kk2], bv[0], bv[1]);
                mma16816(O[jj * 2 + 1], ph[kk2], bv[2], bv[3]);
            }
        }
        __syncthreads();
    }

    // write partials: [bh][row][split][66] = (m, l, acc[64])
    int r0 = w * 16 + (lane >> 2);
    size_t base0 = (((size_t)bh * LLAT + r0) * nsplit + split) * 66;
    size_t base1 = (((size_t)bh * LLAT + r0 + 8) * nsplit + split) * 66;
    if ((lane & 3) == 0) {
        part[base0] = m0; part[base0 + 1] = l0;
        part[base1] = m1; part[base1 + 1] = l1;
    }
    #pragma unroll
    for (int j = 0; j < 8; j++) {
        int col = j * 8 + (lane & 3) * 2;
        part[base0 + 2 + col]     = O[j][0];
        part[base0 + 2 + col + 1] = O[j][1];
        part[base1 + 2 + col]     = O[j][2];
        part[base1 + 2 + col + 1] = O[j][3];
    }
}

// ---------------------------------------------------------------------------
// Combine split-KV partials -> fp16 attention output
// ---------------------------------------------------------------------------
__global__ __launch_bounds__(64) void combine_f16_kernel(
    const float* __restrict__ part, __half* __restrict__ out, int nsplit)
{
    int idx = blockIdx.x;
    int i  = idx & (LLAT - 1);
    int bh = idx >> 7;
    int b = bh >> 3, h = bh & 7;
    int d = threadIdx.x;
    size_t base = (size_t)idx * nsplit * 66;
    float M = -INFINITY;
    for (int s = 0; s < nsplit; s++) M = fmaxf(M, part[base + (size_t)s * 66]);
    float L = 0.0f, o = 0.0f;
    for (int s = 0; s < nsplit; s++) {
        float a = __expf(part[base + (size_t)s * 66] - M);
        L += a * part[base + (size_t)s * 66 + 1];
        o += a * part[base + (size_t)s * 66 + 2 + d];
    }
    out[((size_t)(b * LLAT + i)) * DIM + h * DHEAD + d] = __float2half(o / L);
}

// ---------------------------------------------------------------------------
// LayerNorm (last dim 512) -> fp16
// ---------------------------------------------------------------------------
__global__ __launch_bounds__(128) void ln_f16_kernel(
    const float* __restrict__ x, const float* __restrict__ w,
    const float* __restrict__ b, __half* __restrict__ out)
{
    int row = blockIdx.x;
    int t = threadIdx.x;
    float4 v = reinterpret_cast<const float4*>(x + (size_t)row * DIM)[t];
    float s  = v.x + v.y + v.z + v.w;
    float ss = v.x*v.x + v.y*v.y + v.z*v.z + v.w*v.w;
    #pragma unroll
    for (int o = 16; o > 0; o >>= 1) {
        s  += __shfl_xor_sync(0xffffffffu, s,  o);
        ss += __shfl_xor_sync(0xffffffffu, ss, o);
    }
    __shared__ float rs[4], rss[4];
    int warp = t >> 5;
    if ((t & 31) == 0) { rs[warp] = s; rss[warp] = ss; }
    __syncthreads();
    s  = rs[0] + rs[1] + rs[2] + rs[3];
    ss = rss[0] + rss[1] + rss[2] + rss[3];
    float mu  = s * (1.0f / DIM);
    float var = ss * (1.0f / DIM) - mu * mu;
    float inv = rsqrtf(var + 1e-5f);
    float4 wv = reinterpret_cast<const float4*>(w)[t];
    float4 bv = reinterpret_cast<const float4*>(b)[t];
    __half2 h0 = __floats2half2_rn((v.x - mu) * inv * wv.x + bv.x,
                                   (v.y - mu) * inv * wv.y + bv.y);
    __half2 h1 = __floats2half2_rn((v.z - mu) * inv * wv.z + bv.z,
                                   (v.w - mu) * inv * wv.w + bv.w);
    __half2* op = reinterpret_cast<__half2*>(out + (size_t)row * DIM + t * 4);
    op[0] = h0; op[1] = h1;
}

// ---------------------------------------------------------------------------
// Weight convert + transpose: W[K,N] f32 -> f16 [N,K]
// ---------------------------------------------------------------------------
__global__ __launch_bounds__(256) void wconv_kernel(
    const float* __restrict__ W, __half* __restrict__ out, int K, int N)
{
    __shared__ float tile[32][33];
    int tx = threadIdx.x, ty = threadIdx.y;
    int x = blockIdx.x * 32 + tx;
    int y0 = blockIdx.y * 32;
    #pragma unroll
    for (int j = ty; j < 32; j += 8)
        tile[j][tx] = W[(size_t)(y0 + j) * N + x];
    __syncthreads();
    #pragma unroll
    for (int j = ty; j < 32; j += 8) {
        int n = blockIdx.x * 32 + j;
        int k = y0 + tx;
        out[(size_t)n * K + k] = __float2half(tile[tx][j]);
    }
}

// ---------------------------------------------------------------------------
// GEGLU (exact erf, fp16 in) -> fp16
// ---------------------------------------------------------------------------
__global__ __launch_bounds__(256) void geglu_f16_kernel(
    const __half* __restrict__ hbuf, __half* __restrict__ out)
{
    int idx = blockIdx.x * blockDim.x + threadIdx.x;
    int row = idx >> 11;
    int c   = idx & 2047;
    float a = __half2float(hbuf[(size_t)row * (2 * FFD) + c]);
    float g = __half2float(hbuf[(size_t)row * (2 * FFD) + FFD + c]);
    float y = a * (0.5f * g * (1.0f + erff(g * 0.70710678118654752f)));
    out[idx] = __float2half(y);
}

// ---------------------------------------------------------------------------
// Host orchestration
// ---------------------------------------------------------------------------
extern "C" void kernel_launch(void* const* d_in, const int* in_sizes, int n_in,
                              void* d_out, int out_size)
{
    (void)in_sizes; (void)n_in; (void)out_size;
    const float* context = (const float*)d_in[0];
    const float* latents = (const float*)d_in[1];
    const float* ca_ln_w  = (const float*)d_in[2];
    const float* ca_ln_b  = (const float*)d_in[3];
    const float* ca_lnc_w = (const float*)d_in[4];
    const float* ca_lnc_b = (const float*)d_in[5];
    const float* ca_wq  = (const float*)d_in[6];
    const float* ca_wkv = (const float*)d_in[7];
    const float* ca_wo  = (const float*)d_in[8];
    const float* ca_bo  = (const float*)d_in[9];
    const float* cf_ln_w = (const float*)d_in[10];
    const float* cf_ln_b = (const float*)d_in[11];
    const float* cf_w1 = (const float*)d_in[12];
    const float* cf_b1 = (const float*)d_in[13];
    const float* cf_w2 = (const float*)d_in[14];
    const float* cf_b2 = (const float*)d_in[15];
    const float* sa_ln_w = (const float*)d_in[16];
    const float* sa_ln_b = (const float*)d_in[17];
    const float* sa_wq  = (const float*)d_in[18];
    const float* sa_wkv = (const float*)d_in[19];
    const float* sa_wo  = (const float*)d_in[20];
    const float* sa_bo  = (const float*)d_in[21];
    const float* lf_ln_w = (const float*)d_in[22];
    const float* lf_ln_b = (const float*)d_in[23];
    const float* lf_w1 = (const float*)d_in[24];
    const float* lf_b1 = (const float*)d_in[25];
    const float* lf_w2 = (const float*)d_in[26];
    const float* lf_b2 = (const float*)d_in[27];

    void* sp = nullptr;
    cudaGetSymbolAddress(&sp, g_scratch);
    unsigned char* S = (unsigned char*)sp;
    __half* kvb = (__half*)(S + SB_KVB);
    __half* hb  = (__half*)(S + SB_HB);
    float* pb   = (float*)(S + SB_PART);
    __half* cnh = (__half*)(S + SB_CNH);
    __half* wh  = (__half*)(S + SB_WH);
    __half* xnh = (__half*)(S + SB_XNH);
    __half* qbh = (__half*)(S + SB_QB);
    __half* aobh= (__half*)(S + SB_AOBH);
    __half* ggh = (__half*)(S + SB_GGH);
    float* x1   = (float*)(S + SB_X1);
    float* x2   = (float*)(S + SB_X2);
    float* x3   = (float*)(S + SB_X3);

    cudaFuncSetAttribute(mmgemm_kernel<false,false,__half>, cudaFuncAttributeMaxDynamicSharedMemorySize, MM_SMEM);
    cudaFuncSetAttribute(mmgemm_kernel<true,false,__half>,  cudaFuncAttributeMaxDynamicSharedMemorySize, MM_SMEM);
    cudaFuncSetAttribute(mmgemm_kernel<true,true,float>,    cudaFuncAttributeMaxDynamicSharedMemorySize, MM_SMEM);
    cudaFuncSetAttribute(flash_tc_kernel, cudaFuncAttributeMaxDynamicSharedMemorySize, FLASH_SMEM);

    const int rowsL = BATCH * LLAT;   // 1024
    const int rowsC = BATCH * NCTX;   // 32768

    // ---- weight convert + transpose ----
    struct WDesc { const float* w; size_t off; int K, N; };
    const WDesc wd[10] = {
        {ca_wq,  WO_CAQ,  512,  512},  {ca_wkv, WO_CAKV, 512, 1024},
        {ca_wo,  WO_CAO,  512,  512},  {cf_w1,  WO_CF1,  512, 4096},
        {cf_w2,  WO_CF2,  2048, 512},  {sa_wq,  WO_SAQ,  512,  512},
        {sa_wkv, WO_SAKV, 512, 1024},  {sa_wo,  WO_SAO,  512,  512},
        {lf_w1,  WO_LF1,  512, 4096},  {lf_w2,  WO_LF2,  2048, 512},
    };
    for (int i = 0; i < 10; i++)
        wconv_kernel<<<dim3(wd[i].N / 32, wd[i].K / 32), dim3(32, 8)>>>(
            wd[i].w, wh + wd[i].off, wd[i].K, wd[i].N);

    // ---- cross attention ----
    ln_f16_kernel<<<rowsL, 128>>>(latents, ca_ln_w, ca_ln_b, xnh);
    ln_f16_kernel<<<rowsC, 128>>>(context, ca_lnc_w, ca_lnc_b, cnh);
    mmgemm_kernel<false,false,__half><<<dim3(4, 8),   256, MM_SMEM>>>(
        xnh, wh + WO_CAQ, nullptr, nullptr, qbh, rowsL, 512, 512);
    mmgemm_kernel<false,false,__half><<<dim3(8, 256), 256, MM_SMEM>>>(
        cnh, wh + WO_CAKV, nullptr, nullptr, kvb, rowsC, 1024, 512);
    flash_tc_kernel<<<dim3(64, 8), 256, FLASH_SMEM>>>(qbh, kvb, pb, NCTX, 8);
    combine_f16_kernel<<<8192, 64>>>(pb, aobh, 8);
    mmgemm_kernel<true,true,float><<<dim3(4, 8), 256, MM_SMEM>>>(
        aobh, wh + WO_CAO, ca_bo, latents, x1, rowsL, 512, 512);

    // ---- cross FFN (GEGLU) ----
    ln_f16_kernel<<<rowsL, 128>>>(x1, cf_ln_w, cf_ln_b, xnh);
    mmgemm_kernel<true,false,__half><<<dim3(32, 8), 256, MM_SMEM>>>(
        xnh, wh + WO_CF1, cf_b1, nullptr, hb, rowsL, 4096, 512);
    geglu_f16_kernel<<<8192, 256>>>(hb, ggh);
    mmgemm_kernel<true,true,float><<<dim3(4, 8), 256, MM_SMEM>>>(
        ggh, wh + WO_CF2, cf_b2, x1, x2, rowsL, 512, 2048);

    // ---- latent self-attention ----
    ln_f16_kernel<<<rowsL, 128>>>(x2, sa_ln_w, sa_ln_b, xnh);
    mmgemm_kernel<false,false,__half><<<dim3(4, 8), 256, MM_SMEM>>>(
        xnh, wh + WO_SAQ, nullptr, nullptr, qbh, rowsL, 512, 512);
    mmgemm_kernel<false,false,__half><<<dim3(8, 8), 256, MM_SMEM>>>(
        xnh, wh + WO_SAKV, nullptr, nullptr, kvb, rowsL, 1024, 512);
    flash_tc_kernel<<<dim3(64, 2), 256, FLASH_SMEM>>>(qbh, kvb, pb, LLAT, 2);
    combine_f16_kernel<<<8192, 64>>>(pb, aobh, 2);
    mmgemm_kernel<true,true,float><<<dim3(4, 8), 256, MM_SMEM>>>(
        aobh, wh + WO_SAO, sa_bo, x2, x3, rowsL, 512, 512);

    // ---- latent FFN (GEGLU) ----
    ln_f16_kernel<<<rowsL, 128>>>(x3, lf_ln_w, lf_ln_b, xnh);
    mmgemm_kernel<true,false,__half><<<dim3(32, 8), 256, MM_SMEM>>>(
        xnh, wh + WO_LF1, lf_b1, nullptr, hb, rowsL, 4096, 512);
    geglu_f16_kernel<<<8192, 256>>>(hb, ggh);
    mmgemm_kernel<true,true,float><<<dim3(4, 8), 256, MM_SMEM>>>(
        ggh, wh + WO_LF2, lf_b2, x3, (float*)d_out, rowsL, 512, 2048);
}

// round 6
// speedup vs baseline: 4.7915x; 1.0339x over previous
#include <cuda_runtime.h>
#include <cuda_fp16.h>
#include <math.h>
#include <stdint.h>

// ---------------------------------------------------------------------------
// Problem constants
// ---------------------------------------------------------------------------
#define DIM   512
#define NHEAD 8
#define DHEAD 64
#define BATCH 8
#define LLAT  128
#define NCTX  4096
#define FFD   2048
#define ATT_SCALE 0.125f
#define LOG2E 1.44269504f

// ---------------------------------------------------------------------------
// Scratch (bytes, all offsets 1024-aligned)
// ---------------------------------------------------------------------------
#define SB_KVB   0ull            // f16 [32768,1024]   67108864
#define SB_HB    134217728ull    // f16 [1024,4096]     8388608
#define SB_PART  150994944ull    // f32 partials       17301504
#define SB_CNH   168296448ull    // f16 [32768,512]    33554432
#define SB_WH    201850880ull    // f16 packed transposed weights 16777216
#define SB_XNH   218628096ull    // f16 [1024,512]      1048576
#define SB_QB    219676672ull    // f16 [1024,512]      1048576
#define SB_AOBH  221773824ull    // f16 [1024,512]      1048576
#define SB_GGH   222822400ull    // f16 [1024,2048]     4194304
#define SB_X1    227016704ull    // f32 [1024,512]      2097152
#define SB_X2    229113856ull
#define SB_X3    231211008ull
#define SCRATCH_BYTES 233308160ull

__device__ __align__(1024) unsigned char g_scratch[SCRATCH_BYTES];

// Packed transposed-weight element offsets (f16 elements)
#define WO_CAQ   0ull
#define WO_CAKV  262144ull
#define WO_CAO   786432ull
#define WO_CF1   1048576ull
#define WO_CF2   3145728ull
#define WO_SAQ   4194304ull
#define WO_SAKV  4456448ull
#define WO_SAO   4980736ull
#define WO_LF1   5242880ull
#define WO_LF2   7340032ull

// ---------------------------------------------------------------------------
// Low-level helpers
// ---------------------------------------------------------------------------
__device__ __forceinline__ uint32_t smem_u32(const void* p) {
    uint32_t a;
    asm("{ .reg .u64 t; cvta.to.shared.u64 t, %1; cvt.u32.u64 %0, t; }" : "=r"(a) : "l"(p));
    return a;
}
__device__ __forceinline__ void cp16(uint32_t dst, const void* src) {
    asm volatile("cp.async.cg.shared.global [%0], [%1], 16;" :: "r"(dst), "l"(src) : "memory");
}
#define CP_COMMIT() asm volatile("cp.async.commit_group;" ::: "memory")
#define CP_WAIT(n)  asm volatile("cp.async.wait_group %0;" :: "n"(n) : "memory")

__device__ __forceinline__ void ldm_x4(uint32_t* r, uint32_t addr) {
    asm volatile("ldmatrix.sync.aligned.m8n8.x4.shared.b16 {%0,%1,%2,%3}, [%4];"
        : "=r"(r[0]), "=r"(r[1]), "=r"(r[2]), "=r"(r[3]) : "r"(addr));
}
__device__ __forceinline__ void ldm_x4_t(uint32_t* r, uint32_t addr) {
    asm volatile("ldmatrix.sync.aligned.m8n8.x4.trans.shared.b16 {%0,%1,%2,%3}, [%4];"
        : "=r"(r[0]), "=r"(r[1]), "=r"(r[2]), "=r"(r[3]) : "r"(addr));
}
__device__ __forceinline__ void mma16816(float* c, const uint32_t* a, uint32_t b0, uint32_t b1) {
    asm volatile("mma.sync.aligned.m16n8k16.row.col.f32.f16.f16.f32 "
        "{%0,%1,%2,%3}, {%4,%5,%6,%7}, {%8,%9}, {%0,%1,%2,%3};"
        : "+f"(c[0]), "+f"(c[1]), "+f"(c[2]), "+f"(c[3])
        : "r"(a[0]), "r"(a[1]), "r"(a[2]), "r"(a[3]), "r"(b0), "r"(b1));
}
__device__ __forceinline__ float ex2(float x) {
    float y; asm("ex2.approx.f32 %0, %1;" : "=f"(y) : "f"(x)); return y;
}
__device__ __forceinline__ uint32_t packh2(float a, float b) {
    __half2 h = __floats2half2_rn(a, b);
    return *reinterpret_cast<uint32_t*>(&h);
}
__device__ __forceinline__ void store2(float* p, float2 v) {
    *reinterpret_cast<float2*>(p) = v;
}
__device__ __forceinline__ void store2(__half* p, float2 v) {
    *reinterpret_cast<__half2*>(p) = __floats2half2_rn(v.x, v.y);
}

// ---------------------------------------------------------------------------
// fp16 tensor-core GEMM, CTA tile 128x128 (8 warps, 3-stage cp.async)
// C[M,N] = A[M,K] @ B[N,K]^T (+bias)(+res)
// ---------------------------------------------------------------------------
#define ROW_ELEMS 40
#define OP_BYTES  (128 * ROW_ELEMS * 2)
#define STAGE_BYTES (2 * OP_BYTES)
#define MM_STAGES 3
#define MM_SMEM (MM_STAGES * STAGE_BYTES)

__device__ __forceinline__ void mm_load_stage(
    uint32_t sbase, const __half* __restrict__ A, const __half* __restrict__ B,
    int bm, int bn, int K, int k0, int tid)
{
    #pragma unroll
    for (int o = 0; o < 2; o++) {
        const __half* base = o ? B : A;
        int g0 = o ? bn : bm;
        #pragma unroll
        for (int h = 0; h < 2; h++) {
            int idx = h * 256 + tid;
            int row = idx >> 2, c = idx & 3;
            cp16(sbase + o * OP_BYTES + row * (ROW_ELEMS * 2) + c * 16,
                 base + (size_t)(g0 + row) * K + k0 + c * 8);
        }
    }
}

__device__ __forceinline__ void mm_compute_stage(
    uint32_t sbase, float (&acc)[2][8][4], int wm, int wn, int lane)
{
    const uint32_t aA = sbase;
    const uint32_t aB = sbase + OP_BYTES;
    int arow = lane & 15;
    int acolg = lane >> 4;
    int brow = ((lane >> 4) << 3) + (lane & 7);
    int bcolg = (lane >> 3) & 1;
    #pragma unroll
    for (int kk = 0; kk < 2; kk++) {
        int k0 = kk * 16;
        uint32_t af[2][4];
        #pragma unroll
        for (int mb = 0; mb < 2; mb++) {
            uint32_t off = (uint32_t)((wm * 32 + mb * 16 + arow) * ROW_ELEMS + k0 + acolg * 8) * 2;
            ldm_x4(af[mb], aA + off);
        }
        uint32_t bfm[4][4];
        #pragma unroll
        for (int j = 0; j < 4; j++) {
            uint32_t off = (uint32_t)((wn * 64 + j * 16 + brow) * ROW_ELEMS + k0 + bcolg * 8) * 2;
            ldm_x4(bfm[j], aB + off);
        }
        #pragma unroll
        for (int mb = 0; mb < 2; mb++)
            #pragma unroll
            for (int j = 0; j < 4; j++)
                #pragma unroll
                for (int p = 0; p < 2; p++)
                    mma16816(acc[mb][j * 2 + p], af[mb], bfm[j][p * 2], bfm[j][p * 2 + 1]);
    }
}

template<bool BIAS, bool RES, typename OutT>
__global__ __launch_bounds__(256) void mmgemm_kernel(
    const __half* __restrict__ A, const __half* __restrict__ B,
    const float* __restrict__ bias, const float* __restrict__ res,
    OutT* __restrict__ C, int M, int N, int K)
{
    extern __shared__ __align__(128) char smem[];
    uint32_t sb = smem_u32(smem);
    int tid = threadIdx.x;
    int wid = tid >> 5, lane = tid & 31;
    int wm = wid >> 1, wn = wid & 1;
    int bm = blockIdx.y * 128, bn = blockIdx.x * 128;

    float acc[2][8][4];
    #pragma unroll
    for (int a = 0; a < 2; a++)
        #pragma unroll
        for (int b = 0; b < 8; b++)
            #pragma unroll
            for (int c = 0; c < 4; c++) acc[a][b][c] = 0.0f;

    const int NC = K >> 5;
    mm_load_stage(sb, A, B, bm, bn, K, 0, tid);
    CP_COMMIT();
    if (NC > 1) {
        mm_load_stage(sb + STAGE_BYTES, A, B, bm, bn, K, 32, tid);
        CP_COMMIT();
    }
    for (int c = 0; c < NC; c++) {
        if (c + 2 < NC) CP_WAIT(1); else CP_WAIT(0);
        __syncthreads();
        if (c + 2 < NC) {
            mm_load_stage(sb + ((c + 2) % MM_STAGES) * STAGE_BYTES, A, B, bm, bn, K, (c + 2) << 5, tid);
            CP_COMMIT();
        }
        mm_compute_stage(sb + (c % MM_STAGES) * STAGE_BYTES, acc, wm, wn, lane);
    }

    int lane4 = lane >> 2;
    int lane2 = (lane & 3) << 1;
    #pragma unroll
    for (int mb = 0; mb < 2; mb++) {
        int r0 = bm + wm * 32 + mb * 16 + lane4;
        #pragma unroll
        for (int nb = 0; nb < 8; nb++) {
            int cc = bn + wn * 64 + nb * 8 + lane2;
            float* a = acc[mb][nb];
            float2 v0 = make_float2(a[0], a[1]);
            float2 v1 = make_float2(a[2], a[3]);
            if (BIAS) {
                float2 bb = *reinterpret_cast<const float2*>(bias + cc);
                v0.x += bb.x; v0.y += bb.y; v1.x += bb.x; v1.y += bb.y;
            }
            size_t o0 = (size_t)r0 * N + cc;
            size_t o1 = (size_t)(r0 + 8) * N + cc;
            if (RES) {
                float2 rr = *reinterpret_cast<const float2*>(res + o0);
                v0.x += rr.x; v0.y += rr.y;
                rr = *reinterpret_cast<const float2*>(res + o1);
                v1.x += rr.x; v1.y += rr.y;
            }
            store2(C + o0, v0);
            store2(C + o1, v1);
        }
    }
}

// ---------------------------------------------------------------------------
// fp16 tensor-core GEMM, CTA tile 64x64 (4 warps, 3-stage cp.async)
// For small-M GEMMs: 4x more CTAs than the 128 tile.
// ---------------------------------------------------------------------------
#define OP64_BYTES  (64 * ROW_ELEMS * 2)      // 5120
#define STAGE64     (2 * OP64_BYTES)          // 10240
#define MM64_SMEM   (MM_STAGES * STAGE64)     // 30720

__device__ __forceinline__ void mm64_load_stage(
    uint32_t sbase, const __half* __restrict__ A, const __half* __restrict__ B,
    int bm, int bn, int K, int k0, int tid)
{
    #pragma unroll
    for (int o = 0; o < 2; o++) {
        const __half* base = o ? B : A;
        int g0 = o ? bn : bm;
        #pragma unroll
        for (int h = 0; h < 2; h++) {
            int idx = h * 128 + tid;          // 0..255 16B chunks
            int row = idx >> 2, c = idx & 3;
            cp16(sbase + o * OP64_BYTES + row * (ROW_ELEMS * 2) + c * 16,
                 base + (size_t)(g0 + row) * K + k0 + c * 8);
        }
    }
}

__device__ __forceinline__ void mm64_compute_stage(
    uint32_t sbase, float (&acc)[2][4][4], int wm, int wn, int lane)
{
    const uint32_t aA = sbase;
    const uint32_t aB = sbase + OP64_BYTES;
    int arow = lane & 15;
    int acolg = lane >> 4;
    int brow = ((lane >> 4) << 3) + (lane & 7);
    int bcolg = (lane >> 3) & 1;
    #pragma unroll
    for (int kk = 0; kk < 2; kk++) {
        int k0 = kk * 16;
        uint32_t af[2][4];
        #pragma unroll
        for (int mb = 0; mb < 2; mb++) {
            uint32_t off = (uint32_t)((wm * 32 + mb * 16 + arow) * ROW_ELEMS + k0 + acolg * 8) * 2;
            ldm_x4(af[mb], aA + off);
        }
        uint32_t bfm[2][4];
        #pragma unroll
        for (int j = 0; j < 2; j++) {
            uint32_t off = (uint32_t)((wn * 32 + j * 16 + brow) * ROW_ELEMS + k0 + bcolg * 8) * 2;
            ldm_x4(bfm[j], aB + off);
        }
        #pragma unroll
        for (int mb = 0; mb < 2; mb++)
            #pragma unroll
            for (int j = 0; j < 2; j++)
                #pragma unroll
                for (int p = 0; p < 2; p++)
                    mma16816(acc[mb][j * 2 + p], af[mb], bfm[j][p * 2], bfm[j][p * 2 + 1]);
    }
}

template<bool BIAS, bool RES, typename OutT>
__global__ __launch_bounds__(128) void mm64gemm_kernel(
    const __half* __restrict__ A, const __half* __restrict__ B,
    const float* __restrict__ bias, const float* __restrict__ res,
    OutT* __restrict__ C, int M, int N, int K)
{
    extern __shared__ __align__(128) char smem[];
    uint32_t sb = smem_u32(smem);
    int tid = threadIdx.x;
    int wid = tid >> 5, lane = tid & 31;
    int wm = wid >> 1, wn = wid & 1;
    int bm = blockIdx.y * 64, bn = blockIdx.x * 64;

    float acc[2][4][4];
    #pragma unroll
    for (int a = 0; a < 2; a++)
        #pragma unroll
        for (int b = 0; b < 4; b++)
            #pragma unroll
            for (int c = 0; c < 4; c++) acc[a][b][c] = 0.0f;

    const int NC = K >> 5;
    mm64_load_stage(sb, A, B, bm, bn, K, 0, tid);
    CP_COMMIT();
    if (NC > 1) {
        mm64_load_stage(sb + STAGE64, A, B, bm, bn, K, 32, tid);
        CP_COMMIT();
    }
    for (int c = 0; c < NC; c++) {
        if (c + 2 < NC) CP_WAIT(1); else CP_WAIT(0);
        __syncthreads();
        if (c + 2 < NC) {
            mm64_load_stage(sb + ((c + 2) % MM_STAGES) * STAGE64, A, B, bm, bn, K, (c + 2) << 5, tid);
            CP_COMMIT();
        }
        mm64_compute_stage(sb + (c % MM_STAGES) * STAGE64, acc, wm, wn, lane);
    }

    int lane4 = lane >> 2;
    int lane2 = (lane & 3) << 1;
    #pragma unroll
    for (int mb = 0; mb < 2; mb++) {
        int r0 = bm + wm * 32 + mb * 16 + lane4;
        #pragma unroll
        for (int nb = 0; nb < 4; nb++) {
            int cc = bn + wn * 32 + nb * 8 + lane2;
            float* a = acc[mb][nb];
            float2 v0 = make_float2(a[0], a[1]);
            float2 v1 = make_float2(a[2], a[3]);
            if (BIAS) {
                float2 bb = *reinterpret_cast<const float2*>(bias + cc);
                v0.x += bb.x; v0.y += bb.y; v1.x += bb.x; v1.y += bb.y;
            }
            size_t o0 = (size_t)r0 * N + cc;
            size_t o1 = (size_t)(r0 + 8) * N + cc;
            if (RES) {
                float2 rr = *reinterpret_cast<const float2*>(res + o0);
                v0.x += rr.x; v0.y += rr.y;
                rr = *reinterpret_cast<const float2*>(res + o1);
                v1.x += rr.x; v1.y += rr.y;
            }
            store2(C + o0, v0);
            store2(C + o1, v1);
        }
    }
}

// ---------------------------------------------------------------------------
// Tensor-core flash attention (fp16 QKV, fp32 online softmax, split-KV)
// ---------------------------------------------------------------------------
#define FPAD 72
#define FQ_BYTES   (128 * FPAD * 2)
#define FKV_BYTES  (64 * FPAD * 2)
#define FSTAGE     (2 * FKV_BYTES)
#define FLASH_SMEM (FQ_BYTES + 2 * FSTAGE)

__device__ __forceinline__ void flash_load_tile(
    uint32_t stage, const __half* __restrict__ kvbase, int key0, int tid)
{
    #pragma unroll
    for (int i = 0; i < 4; i++) {
        int idx = i * 256 + tid;
        int o = idx >> 9;
        int key = (idx >> 3) & 63;
        int c = idx & 7;
        cp16(stage + o * FKV_BYTES + (key * FPAD + c * 8) * 2,
             kvbase + (size_t)(key0 + key) * (2 * DIM) + o * DIM + c * 8);
    }
}

__global__ __launch_bounds__(256) void flash_tc_kernel(
    const __half* __restrict__ Q, const __half* __restrict__ KV,
    float* __restrict__ part, int Nk, int nsplit)
{
    extern __shared__ __align__(128) char fsm[];
    uint32_t sb = smem_u32(fsm);
    const uint32_t Qs = sb;

    int bh = blockIdx.x;
    int b = bh >> 3, h = bh & 7;
    int split = blockIdx.y;
    int chunk = Nk / nsplit;
    int j0 = split * chunk;
    int ntiles = chunk >> 6;
    int tid = threadIdx.x, w = tid >> 5, lane = tid & 31;

    const __half* qbase  = Q  + (size_t)(b * LLAT) * DIM + h * DHEAD;
    const __half* kvbase = KV + (size_t)b * Nk * (2 * DIM) + h * DHEAD;

    #pragma unroll
    for (int i = 0; i < 4; i++) {
        int idx = i * 256 + tid;
        int row = idx >> 3, c = idx & 7;
        cp16(Qs + (row * FPAD + c * 8) * 2, qbase + (size_t)row * DIM + c * 8);
    }
    flash_load_tile(sb + FQ_BYTES, kvbase, j0, tid);
    CP_COMMIT();

    float O[8][4];
    #pragma unroll
    for (int j = 0; j < 8; j++)
        #pragma unroll
        for (int r = 0; r < 4; r++) O[j][r] = 0.0f;
    uint32_t qf[4][4];
    float m0 = -INFINITY, m1 = -INFINITY, l0 = 0.0f, l1 = 0.0f;

    int arow = lane & 15, acolg = lane >> 4;
    int brow = ((lane >> 4) << 3) + (lane & 7), bcolg = (lane >> 3) & 1;
    int krow = (((lane >> 3) & 1) << 3) + (lane & 7), ncolg = lane >> 4;
    const float k2 = ATT_SCALE * LOG2E;

    for (int t = 0; t < ntiles; t++) {
        if (t + 1 < ntiles) {
            flash_load_tile(sb + FQ_BYTES + ((t + 1) & 1) * FSTAGE, kvbase, j0 + (t + 1) * 64, tid);
            CP_COMMIT();
            CP_WAIT(1);
        } else {
            CP_WAIT(0);
        }
        __syncthreads();
        if (t == 0) {
            #pragma unroll
            for (int kk = 0; kk < 4; kk++)
                ldm_x4(qf[kk], Qs + ((w * 16 + arow) * FPAD + kk * 16 + acolg * 8) * 2);
        }
        uint32_t Kt = sb + FQ_BYTES + (t & 1) * FSTAGE;
        uint32_t Vt = Kt + FKV_BYTES;

        float S[8][4];
        #pragma unroll
        for (int j = 0; j < 8; j++)
            #pragma unroll
            for (int r = 0; r < 4; r++) S[j][r] = 0.0f;
        #pragma unroll
        for (int kk = 0; kk < 4; kk++) {
            #pragma unroll
            for (int jj = 0; jj < 4; jj++) {
                uint32_t bk[4];
                ldm_x4(bk, Kt + ((jj * 16 + brow) * FPAD + kk * 16 + bcolg * 8) * 2);
                mma16816(S[jj * 2],     qf[kk], bk[0], bk[1]);
                mma16816(S[jj * 2 + 1], qf[kk], bk[2], bk[3]);
            }
        }

        float t0 = -INFINITY, t1 = -INFINITY;
        #pragma unroll
        for (int j = 0; j < 8; j++) {
            t0 = fmaxf(t0, fmaxf(S[j][0], S[j][1]));
            t1 = fmaxf(t1, fmaxf(S[j][2], S[j][3]));
        }
        #pragma unroll
        for (int o = 1; o < 4; o <<= 1) {
            t0 = fmaxf(t0, __shfl_xor_sync(0xffffffffu, t0, o));
            t1 = fmaxf(t1, __shfl_xor_sync(0xffffffffu, t1, o));
        }
        float m0n = fmaxf(m0, t0 * ATT_SCALE);
        float m1n = fmaxf(m1, t1 * ATT_SCALE);
        float corr0 = ex2((m0 - m0n) * LOG2E);
        float corr1 = ex2((m1 - m1n) * LOG2E);
        l0 *= corr0; l1 *= corr1;
        #pragma unroll
        for (int j = 0; j < 8; j++) {
            O[j][0] *= corr0; O[j][1] *= corr0;
            O[j][2] *= corr1; O[j][3] *= corr1;
        }
        float mb0 = m0n * LOG2E, mb1 = m1n * LOG2E;
        float ps0 = 0.0f, ps1 = 0.0f;
        uint32_t ph[4][4];
        #pragma unroll
        for (int kk2 = 0; kk2 < 4; kk2++) {
            int ja = 2 * kk2, jb = ja + 1;
            float pa0 = ex2(fmaf(S[ja][0], k2, -mb0));
            float pa1 = ex2(fmaf(S[ja][1], k2, -mb0));
            float pa2 = ex2(fmaf(S[ja][2], k2, -mb1));
            float pa3 = ex2(fmaf(S[ja][3], k2, -mb1));
            float pb0 = ex2(fmaf(S[jb][0], k2, -mb0));
            float pb1 = ex2(fmaf(S[jb][1], k2, -mb0));
            float pb2 = ex2(fmaf(S[jb][2], k2, -mb1));
            float pb3 = ex2(fmaf(S[jb][3], k2, -mb1));
            ps0 += pa0 + pa1 + pb0 + pb1;
            ps1 += pa2 + pa3 + pb2 + pb3;
            ph[kk2][0] = packh2(pa0, pa1);
            ph[kk2][1] = packh2(pa2, pa3);
            ph[kk2][2] = packh2(pb0, pb1);
            ph[kk2][3] = packh2(pb2, pb3);
        }
        #pragma unroll
        for (int o = 1; o < 4; o <<= 1) {
            ps0 += __shfl_xor_sync(0xffffffffu, ps0, o);
            ps1 += __shfl_xor_sync(0xffffffffu, ps1, o);
        }
        l0 += ps0; l1 += ps1;
        m0 = m0n; m1 = m1n;

        #pragma unroll
        for (int kk2 = 0; kk2 < 4; kk2++) {
            #pragma unroll
            for (int jj = 0; jj < 4; jj++) {
                uint32_t bv[4];
                ldm_x4_t(bv, Vt + ((kk2 * 16 + krow) * FPAD + jj * 16 + ncolg * 8) * 2);
                mma16816(O[jj * 2],     ph[kk2], bv[0], bv[1]);
                mma16816(O[jj * 2 + 1], ph[kk2], bv[2], bv[3]);
            }
        }
        __syncthreads();
    }

    int r0 = w * 16 + (lane >> 2);
    size_t base0 = (((size_t)bh * LLAT + r0) * nsplit + split) * 66;
    size_t base1 = (((size_t)bh * LLAT + r0 + 8) * nsplit + split) * 66;
    if ((lane & 3) == 0) {
        part[base0] = m0; part[base0 + 1] = l0;
        part[base1] = m1; part[base1 + 1] = l1;
    }
    #pragma unroll
    for (int j = 0; j < 8; j++) {
        int col = j * 8 + (lane & 3) * 2;
        part[base0 + 2 + col]     = O[j][0];
        part[base0 + 2 + col + 1] = O[j][1];
        part[base1 + 2 + col]     = O[j][2];
        part[base1 + 2 + col + 1] = O[j][3];
    }
}

// ---------------------------------------------------------------------------
// Combine split-KV partials -> fp16 attention output
// ---------------------------------------------------------------------------
__global__ __launch_bounds__(64) void combine_f16_kernel(
    const float* __restrict__ part, __half* __restrict__ out, int nsplit)
{
    int idx = blockIdx.x;
    int i  = idx & (LLAT - 1);
    int bh = idx >> 7;
    int b = bh >> 3, h = bh & 7;
    int d = threadIdx.x;
    size_t base = (size_t)idx * nsplit * 66;
    float M = -INFINITY;
    for (int s = 0; s < nsplit; s++) M = fmaxf(M, part[base + (size_t)s * 66]);
    float L = 0.0f, o = 0.0f;
    for (int s = 0; s < nsplit; s++) {
        float a = __expf(part[base + (size_t)s * 66] - M);
        L += a * part[base + (size_t)s * 66 + 1];
        o += a * part[base + (size_t)s * 66 + 2 + d];
    }
    out[((size_t)(b * LLAT + i)) * DIM + h * DHEAD + d] = __float2half(o / L);
}

// ---------------------------------------------------------------------------
// LayerNorm (last dim 512) -> fp16
// ---------------------------------------------------------------------------
__global__ __launch_bounds__(128) void ln_f16_kernel(
    const float* __restrict__ x, const float* __restrict__ w,
    const float* __restrict__ b, __half* __restrict__ out)
{
    int row = blockIdx.x;
    int t = threadIdx.x;
    float4 v = reinterpret_cast<const float4*>(x + (size_t)row * DIM)[t];
    float s  = v.x + v.y + v.z + v.w;
    float ss = v.x*v.x + v.y*v.y + v.z*v.z + v.w*v.w;
    #pragma unroll
    for (int o = 16; o > 0; o >>= 1) {
        s  += __shfl_xor_sync(0xffffffffu, s,  o);
        ss += __shfl_xor_sync(0xffffffffu, ss, o);
    }
    __shared__ float rs[4], rss[4];
    int warp = t >> 5;
    if ((t & 31) == 0) { rs[warp] = s; rss[warp] = ss; }
    __syncthreads();
    s  = rs[0] + rs[1] + rs[2] + rs[3];
    ss = rss[0] + rss[1] + rss[2] + rss[3];
    float mu  = s * (1.0f / DIM);
    float var = ss * (1.0f / DIM) - mu * mu;
    float inv = rsqrtf(var + 1e-5f);
    float4 wv = reinterpret_cast<const float4*>(w)[t];
    float4 bv = reinterpret_cast<const float4*>(b)[t];
    __half2 h0 = __floats2half2_rn((v.x - mu) * inv * wv.x + bv.x,
                                   (v.y - mu) * inv * wv.y + bv.y);
    __half2 h1 = __floats2half2_rn((v.z - mu) * inv * wv.z + bv.z,
                                   (v.w - mu) * inv * wv.w + bv.w);
    __half2* op = reinterpret_cast<__half2*>(out + (size_t)row * DIM + t * 4);
    op[0] = h0; op[1] = h1;
}

// ---------------------------------------------------------------------------
// Batched weight convert + transpose: all 10 matrices, one launch.
// grid = 8192 tiles of 32x32; compile-time descriptor table.
// ---------------------------------------------------------------------------
__global__ __launch_bounds__(256) void wconv_all_kernel(
    const float* w0, const float* w1, const float* w2, const float* w3,
    const float* w4, const float* w5, const float* w6, const float* w7,
    const float* w8, const float* w9, __half* __restrict__ out)
{
    const int   cum[10]  = {256, 768, 1024, 3072, 4096, 4352, 4864, 5120, 7168, 8192};
    const int   Ks[10]   = {512, 512, 512, 512, 2048, 512, 512, 512, 512, 2048};
    const int   Ns[10]   = {512, 1024, 512, 4096, 512, 512, 1024, 512, 4096, 512};
    const size_t offs[10] = {WO_CAQ, WO_CAKV, WO_CAO, WO_CF1, WO_CF2,
                             WO_SAQ, WO_SAKV, WO_SAO, WO_LF1, WO_LF2};
    const float* ws[10] = {w0, w1, w2, w3, w4, w5, w6, w7, w8, w9};

    int bid = blockIdx.x;
    int mi = 0;
    #pragma unroll
    for (int i = 0; i < 9; i++) if (bid >= cum[i]) mi = i + 1;
    int base = (mi == 0) ? 0 : cum[mi - 1];
    int t = bid - base;
    int K = Ks[mi], N = Ns[mi];
    int tilesX = N >> 5;
    int bx = t % tilesX, by = t / tilesX;
    const float* W = ws[mi];
    __half* O = out + offs[mi];

    __shared__ float tile[32][33];
    int tx = threadIdx.x & 31, ty = threadIdx.x >> 5;
    int x = bx * 32 + tx;
    int y0 = by * 32;
    #pragma unroll
    for (int j = ty; j < 32; j += 8)
        tile[j][tx] = W[(size_t)(y0 + j) * N + x];
    __syncthreads();
    #pragma unroll
    for (int j = ty; j < 32; j += 8) {
        int n = bx * 32 + j;
        int k = y0 + tx;
        O[(size_t)n * K + k] = __float2half(tile[tx][j]);
    }
}

// ---------------------------------------------------------------------------
// GEGLU (exact erf, fp16 in) -> fp16
// ---------------------------------------------------------------------------
__global__ __launch_bounds__(256) void geglu_f16_kernel(
    const __half* __restrict__ hbuf, __half* __restrict__ out)
{
    int idx = blockIdx.x * blockDim.x + threadIdx.x;
    int row = idx >> 11;
    int c   = idx & 2047;
    float a = __half2float(hbuf[(size_t)row * (2 * FFD) + c]);
    float g = __half2float(hbuf[(size_t)row * (2 * FFD) + FFD + c]);
    float y = a * (0.5f * g * (1.0f + erff(g * 0.70710678118654752f)));
    out[idx] = __float2half(y);
}

// ---------------------------------------------------------------------------
// Host orchestration
// ---------------------------------------------------------------------------
extern "C" void kernel_launch(void* const* d_in, const int* in_sizes, int n_in,
                              void* d_out, int out_size)
{
    (void)in_sizes; (void)n_in; (void)out_size;
    const float* context = (const float*)d_in[0];
    const float* latents = (const float*)d_in[1];
    const float* ca_ln_w  = (const float*)d_in[2];
    const float* ca_ln_b  = (const float*)d_in[3];
    const float* ca_lnc_w = (const float*)d_in[4];
    const float* ca_lnc_b = (const float*)d_in[5];
    const float* ca_wq  = (const float*)d_in[6];
    const float* ca_wkv = (const float*)d_in[7];
    const float* ca_wo  = (const float*)d_in[8];
    const float* ca_bo  = (const float*)d_in[9];
    const float* cf_ln_w = (const float*)d_in[10];
    const float* cf_ln_b = (const float*)d_in[11];
    const float* cf_w1 = (const float*)d_in[12];
    const float* cf_b1 = (const float*)d_in[13];
    const float* cf_w2 = (const float*)d_in[14];
    const float* cf_b2 = (const float*)d_in[15];
    const float* sa_ln_w = (const float*)d_in[16];
    const float* sa_ln_b = (const float*)d_in[17];
    const float* sa_wq  = (const float*)d_in[18];
    const float* sa_wkv = (const float*)d_in[19];
    const float* sa_wo  = (const float*)d_in[20];
    const float* sa_bo  = (const float*)d_in[21];
    const float* lf_ln_w = (const float*)d_in[22];
    const float* lf_ln_b = (const float*)d_in[23];
    const float* lf_w1 = (const float*)d_in[24];
    const float* lf_b1 = (const float*)d_in[25];
    const float* lf_w2 = (const float*)d_in[26];
    const float* lf_b2 = (const float*)d_in[27];

    void* sp = nullptr;
    cudaGetSymbolAddress(&sp, g_scratch);
    unsigned char* S = (unsigned char*)sp;
    __half* kvb = (__half*)(S + SB_KVB);
    __half* hb  = (__half*)(S + SB_HB);
    float* pb   = (float*)(S + SB_PART);
    __half* cnh = (__half*)(S + SB_CNH);
    __half* wh  = (__half*)(S + SB_WH);
    __half* xnh = (__half*)(S + SB_XNH);
    __half* qbh = (__half*)(S + SB_QB);
    __half* aobh= (__half*)(S + SB_AOBH);
    __half* ggh = (__half*)(S + SB_GGH);
    float* x1   = (float*)(S + SB_X1);
    float* x2   = (float*)(S + SB_X2);
    float* x3   = (float*)(S + SB_X3);

    cudaFuncSetAttribute(mmgemm_kernel<false,false,__half>, cudaFuncAttributeMaxDynamicSharedMemorySize, MM_SMEM);
    cudaFuncSetAttribute(mmgemm_kernel<true,false,__half>,  cudaFuncAttributeMaxDynamicSharedMemorySize, MM_SMEM);
    cudaFuncSetAttribute(flash_tc_kernel, cudaFuncAttributeMaxDynamicSharedMemorySize, FLASH_SMEM);

    const int rowsL = BATCH * LLAT;   // 1024
    const int rowsC = BATCH * NCTX;   // 32768

    // ---- launch 0: all weight converts (one kernel) ----
    wconv_all_kernel<<<8192, 256>>>(ca_wq, ca_wkv, ca_wo, cf_w1, cf_w2,
                                    sa_wq, sa_wkv, sa_wo, lf_w1, lf_w2, wh);

    // ---- cross attention (KV GEMM placed early for ncu window) ----
    ln_f16_kernel<<<rowsC, 128>>>(context, ca_lnc_w, ca_lnc_b, cnh);       // 1
    ln_f16_kernel<<<rowsL, 128>>>(latents, ca_ln_w, ca_ln_b, xnh);         // 2
    mmgemm_kernel<false,false,__half><<<dim3(8, 256), 256, MM_SMEM>>>(     // 3: KV GEMM
        cnh, wh + WO_CAKV, nullptr, nullptr, kvb, rowsC, 1024, 512);
    mm64gemm_kernel<false,false,__half><<<dim3(8, 16), 128, MM64_SMEM>>>(  // 4: Q GEMM
        xnh, wh + WO_CAQ, nullptr, nullptr, qbh, rowsL, 512, 512);
    flash_tc_kernel<<<dim3(64, 8), 256, FLASH_SMEM>>>(qbh, kvb, pb, NCTX, 8); // 5
    combine_f16_kernel<<<8192, 64>>>(pb, aobh, 8);
    mm64gemm_kernel<true,true,float><<<dim3(8, 16), 128, MM64_SMEM>>>(
        aobh, wh + WO_CAO, ca_bo, latents, x1, rowsL, 512, 512);

    // ---- cross FFN (GEGLU) ----
    ln_f16_kernel<<<rowsL, 128>>>(x1, cf_ln_w, cf_ln_b, xnh);
    mmgemm_kernel<true,false,__half><<<dim3(32, 8), 256, MM_SMEM>>>(
        xnh, wh + WO_CF1, cf_b1, nullptr, hb, rowsL, 4096, 512);
    geglu_f16_kernel<<<8192, 256>>>(hb, ggh);
    mm64gemm_kernel<true,true,float><<<dim3(8, 16), 128, MM64_SMEM>>>(
        ggh, wh + WO_CF2, cf_b2, x1, x2, rowsL, 512, 2048);

    // ---- latent self-attention ----
    ln_f16_kernel<<<rowsL, 128>>>(x2, sa_ln_w, sa_ln_b, xnh);
    mm64gemm_kernel<false,false,__half><<<dim3(8, 16), 128, MM64_SMEM>>>(
        xnh, wh + WO_SAQ, nullptr, nullptr, qbh, rowsL, 512, 512);
    mm64gemm_kernel<false,false,__half><<<dim3(16, 16), 128, MM64_SMEM>>>(
        xnh, wh + WO_SAKV, nullptr, nullptr, kvb, rowsL, 1024, 512);
    flash_tc_kernel<<<dim3(64, 2), 256, FLASH_SMEM>>>(qbh, kvb, pb, LLAT, 2);
    combine_f16_kernel<<<8192, 64>>>(pb, aobh, 2);
    mm64gemm_kernel<true,true,float><<<dim3(8, 16), 128, MM64_SMEM>>>(
        aobh, wh + WO_SAO, sa_bo, x2, x3, rowsL, 512, 512);

    // ---- latent FFN (GEGLU) ----
    ln_f16_kernel<<<rowsL, 128>>>(x3, lf_ln_w, lf_ln_b, xnh);
    mmgemm_kernel<true,false,__half><<<dim3(32, 8), 256, MM_SMEM>>>(
        xnh, wh + WO_LF1, lf_b1, nullptr, hb, rowsL, 4096, 512);
    geglu_f16_kernel<<<8192, 256>>>(hb, ggh);
    mm64gemm_kernel<true,true,float><<<dim3(8, 16), 128, MM64_SMEM>>>(
        ggh, wh + WO_LF2, lf_b2, x3, (float*)d_out, rowsL, 512, 2048);
}

// round 8
// speedup vs baseline: 5.0258x; 1.0489x over previous
#include <cuda_runtime.h>
#include <cuda_fp16.h>
#include <math.h>
#include <stdint.h>

// ---------------------------------------------------------------------------
// Problem constants
// ---------------------------------------------------------------------------
#define DIM   512
#define NHEAD 8
#define DHEAD 64
#define BATCH 8
#define LLAT  128
#define NCTX  4096
#define FFD   2048
#define ATT_SCALE 0.125f
#define LOG2E 1.44269504f

// ---------------------------------------------------------------------------
// Scratch (bytes, all offsets 1024-aligned)
// ---------------------------------------------------------------------------
#define SB_KVB   0ull            // f16 [32768,1024]   67108864
#define SB_HB    134217728ull    // f16 [1024,4096]     8388608
#define SB_PART  150994944ull    // f32 partials       17301504
#define SB_CNH   168296448ull    // f16 [32768,512]    33554432
#define SB_WH    201850880ull    // f16 packed transposed weights 16777216
#define SB_XNH   218628096ull    // f16 [1024,512]      1048576
#define SB_QB    219676672ull    // f16 [1024,512]      1048576
#define SB_AOBH  221773824ull    // f16 [1024,512]      1048576
#define SB_GGH   222822400ull    // f16 [1024,2048]     4194304
#define SB_X1    227016704ull    // f32 [1024,512]      2097152
#define SB_X2    229113856ull
#define SB_X3    231211008ull
#define SCRATCH_BYTES 233308160ull

__device__ __align__(1024) unsigned char g_scratch[SCRATCH_BYTES];

// Packed transposed-weight element offsets (f16 elements)
#define WO_CAQ   0ull
#define WO_CAKV  262144ull
#define WO_CAO   786432ull
#define WO_CF1   1048576ull
#define WO_CF2   3145728ull
#define WO_SAQ   4194304ull
#define WO_SAKV  4456448ull
#define WO_SAO   4980736ull
#define WO_LF1   5242880ull
#define WO_LF2   7340032ull

// ---------------------------------------------------------------------------
// Low-level helpers
// ---------------------------------------------------------------------------
__device__ __forceinline__ uint32_t smem_u32(const void* p) {
    uint32_t a;
    asm("{ .reg .u64 t; cvta.to.shared.u64 t, %1; cvt.u32.u64 %0, t; }" : "=r"(a) : "l"(p));
    return a;
}
__device__ __forceinline__ void cp16(uint32_t dst, const void* src) {
    asm volatile("cp.async.cg.shared.global [%0], [%1], 16;" :: "r"(dst), "l"(src) : "memory");
}
#define CP_COMMIT() asm volatile("cp.async.commit_group;" ::: "memory")
#define CP_WAIT(n)  asm volatile("cp.async.wait_group %0;" :: "n"(n) : "memory")

__device__ __forceinline__ void ldm_x4(uint32_t* r, uint32_t addr) {
    asm volatile("ldmatrix.sync.aligned.m8n8.x4.shared.b16 {%0,%1,%2,%3}, [%4];"
        : "=r"(r[0]), "=r"(r[1]), "=r"(r[2]), "=r"(r[3]) : "r"(addr));
}
__device__ __forceinline__ void ldm_x4_t(uint32_t* r, uint32_t addr) {
    asm volatile("ldmatrix.sync.aligned.m8n8.x4.trans.shared.b16 {%0,%1,%2,%3}, [%4];"
        : "=r"(r[0]), "=r"(r[1]), "=r"(r[2]), "=r"(r[3]) : "r"(addr));
}
__device__ __forceinline__ void mma16816(float* c, const uint32_t* a, uint32_t b0, uint32_t b1) {
    asm volatile("mma.sync.aligned.m16n8k16.row.col.f32.f16.f16.f32 "
        "{%0,%1,%2,%3}, {%4,%5,%6,%7}, {%8,%9}, {%0,%1,%2,%3};"
        : "+f"(c[0]), "+f"(c[1]), "+f"(c[2]), "+f"(c[3])
        : "r"(a[0]), "r"(a[1]), "r"(a[2]), "r"(a[3]), "r"(b0), "r"(b1));
}
__device__ __forceinline__ float ex2(float x) {
    float y; asm("ex2.approx.f32 %0, %1;" : "=f"(y) : "f"(x)); return y;
}
__device__ __forceinline__ uint32_t packh2(float a, float b) {
    __half2 h = __floats2half2_rn(a, b);
    return *reinterpret_cast<uint32_t*>(&h);
}
__device__ __forceinline__ void store2(float* p, float2 v) {
    *reinterpret_cast<float2*>(p) = v;
}
__device__ __forceinline__ void store2(__half* p, float2 v) {
    *reinterpret_cast<__half2*>(p) = __floats2half2_rn(v.x, v.y);
}

// ---------------------------------------------------------------------------
// fp16 tensor-core GEMM, CTA tile 128x128, K-step 64, 8 warps (4m x 2n),
// 3-stage cp.async pipeline + in-register fragment double buffering.
// C[M,N] = A[M,K] @ B[N,K]^T (+bias)(+res)
// ---------------------------------------------------------------------------
#define R128 72                                  // 64 + 8 pad (halves)
#define OP_BYTES  (128 * R128 * 2)               // 18432
#define STAGE_BYTES (2 * OP_BYTES)               // 36864: A|B
#define MM_STAGES 3
#define MM_SMEM (MM_STAGES * STAGE_BYTES)        // 110592

__device__ __forceinline__ void mm_load_stage(
    uint32_t sbase, const __half* __restrict__ A, const __half* __restrict__ B,
    int bm, int bn, int K, int k0, int tid)
{
    // 2048 x 16B chunks (A: 1024, B: 1024), 8 per thread
    #pragma unroll
    for (int i = 0; i < 8; i++) {
        int idx = i * 256 + tid;
        int o = idx >> 10;
        int r = (idx >> 3) & 127;
        int c = idx & 7;
        const __half* base = o ? B : A;
        int g0 = o ? bn : bm;
        cp16(sbase + o * OP_BYTES + (r * R128 + c * 8) * 2,
             base + (size_t)(g0 + r) * K + k0 + c * 8);
    }
}

__device__ __forceinline__ void mm_load_frags(
    uint32_t sA, uint32_t sB, uint32_t aOff, uint32_t bOff, int kk,
    uint32_t (&af)[2][4], uint32_t (&bf)[4][4])
{
    uint32_t ka = (uint32_t)kk * 32;   // 16 halves = 32 bytes
    ldm_x4(af[0], sA + aOff + ka);
    ldm_x4(af[1], sA + aOff + 16 * R128 * 2 + ka);
    #pragma unroll
    for (int j = 0; j < 4; j++)
        ldm_x4(bf[j], sB + bOff + j * 16 * R128 * 2 + ka);
}

template<bool BIAS, bool RES, typename OutT>
__global__ __launch_bounds__(256, 2) void mmgemm_kernel(
    const __half* __restrict__ A, const __half* __restrict__ B,
    const float* __restrict__ bias, const float* __restrict__ res,
    OutT* __restrict__ C, int M, int N, int K)
{
    extern __shared__ __align__(128) char smem[];
    uint32_t sb = smem_u32(smem);
    int tid = threadIdx.x;
    int wid = tid >> 5, lane = tid & 31;
    int wm = wid >> 1, wn = wid & 1;
    int bm = blockIdx.y * 128, bn = blockIdx.x * 128;

    float acc[2][8][4];
    #pragma unroll
    for (int a = 0; a < 2; a++)
        #pragma unroll
        for (int b = 0; b < 8; b++)
            #pragma unroll
            for (int c = 0; c < 4; c++) acc[a][b][c] = 0.0f;

    int arow = lane & 15, acolg = lane >> 4;
    int brow = ((lane >> 4) << 3) + (lane & 7), bcolg = (lane >> 3) & 1;
    uint32_t aOff = (uint32_t)((wm * 32 + arow) * R128 + acolg * 8) * 2;
    uint32_t bOff = (uint32_t)((wn * 64 + brow) * R128 + bcolg * 8) * 2;

    const int NC = K >> 6;
    mm_load_stage(sb, A, B, bm, bn, K, 0, tid);
    CP_COMMIT();
    if (NC > 1) {
        mm_load_stage(sb + STAGE_BYTES, A, B, bm, bn, K, 64, tid);
        CP_COMMIT();
    }
    for (int c = 0; c < NC; c++) {
        if (c + 2 < NC) CP_WAIT(1); else CP_WAIT(0);
        __syncthreads();
        if (c + 2 < NC) {
            mm_load_stage(sb + ((c + 2) % MM_STAGES) * STAGE_BYTES, A, B, bm, bn, K, (c + 2) << 6, tid);
            CP_COMMIT();
        }
        uint32_t sA = sb + (c % MM_STAGES) * STAGE_BYTES;
        uint32_t sB = sA + OP_BYTES;

        uint32_t af[2][2][4], bf[2][4][4];
        mm_load_frags(sA, sB, aOff, bOff, 0, af[0], bf[0]);
        #pragma unroll
        for (int kk = 0; kk < 4; kk++) {
            int cur = kk & 1;
            if (kk < 3)
                mm_load_frags(sA, sB, aOff, bOff, kk + 1, af[cur ^ 1], bf[cur ^ 1]);
            #pragma unroll
            for (int mb = 0; mb < 2; mb++)
                #pragma unroll
                for (int j = 0; j < 4; j++) {
                    mma16816(acc[mb][j * 2],     af[cur][mb], bf[cur][j][0], bf[cur][j][1]);
                    mma16816(acc[mb][j * 2 + 1], af[cur][mb], bf[cur][j][2], bf[cur][j][3]);
                }
        }
    }

    int lane4 = lane >> 2;
    int lane2 = (lane & 3) << 1;
    #pragma unroll
    for (int mb = 0; mb < 2; mb++) {
        int r0 = bm + wm * 32 + mb * 16 + lane4;
        #pragma unroll
        for (int nb = 0; nb < 8; nb++) {
            int cc = bn + wn * 64 + nb * 8 + lane2;
            float* a = acc[mb][nb];
            float2 v0 = make_float2(a[0], a[1]);
            float2 v1 = make_float2(a[2], a[3]);
            if (BIAS) {
                float2 bb = *reinterpret_cast<const float2*>(bias + cc);
                v0.x += bb.x; v0.y += bb.y; v1.x += bb.x; v1.y += bb.y;
            }
            size_t o0 = (size_t)r0 * N + cc;
            size_t o1 = (size_t)(r0 + 8) * N + cc;
            if (RES) {
                float2 rr = *reinterpret_cast<const float2*>(res + o0);
                v0.x += rr.x; v0.y += rr.y;
                rr = *reinterpret_cast<const float2*>(res + o1);
                v1.x += rr.x; v1.y += rr.y;
            }
            store2(C + o0, v0);
            store2(C + o1, v1);
        }
    }
}

// ---------------------------------------------------------------------------
// fp16 tensor-core GEMM, CTA tile 64x64 (4 warps, K-step 32, 3 stages)
// For small-M GEMMs.
// ---------------------------------------------------------------------------
#define ROW64 40
#define OP64_BYTES  (64 * ROW64 * 2)          // 5120
#define STAGE64     (2 * OP64_BYTES)          // 10240
#define MM64_SMEM   (MM_STAGES * STAGE64)     // 30720

__device__ __forceinline__ void mm64_load_stage(
    uint32_t sbase, const __half* __restrict__ A, const __half* __restrict__ B,
    int bm, int bn, int K, int k0, int tid)
{
    #pragma unroll
    for (int o = 0; o < 2; o++) {
        const __half* base = o ? B : A;
        int g0 = o ? bn : bm;
        #pragma unroll
        for (int h = 0; h < 2; h++) {
            int idx = h * 128 + tid;
            int row = idx >> 2, c = idx & 3;
            cp16(sbase + o * OP64_BYTES + row * (ROW64 * 2) + c * 16,
                 base + (size_t)(g0 + row) * K + k0 + c * 8);
        }
    }
}

__device__ __forceinline__ void mm64_compute_stage(
    uint32_t sbase, float (&acc)[2][4][4], int wm, int wn, int lane)
{
    const uint32_t aA = sbase;
    const uint32_t aB = sbase + OP64_BYTES;
    int arow = lane & 15;
    int acolg = lane >> 4;
    int brow = ((lane >> 4) << 3) + (lane & 7);
    int bcolg = (lane >> 3) & 1;
    #pragma unroll
    for (int kk = 0; kk < 2; kk++) {
        int k0 = kk * 16;
        uint32_t af[2][4];
        #pragma unroll
        for (int mb = 0; mb < 2; mb++) {
            uint32_t off = (uint32_t)((wm * 32 + mb * 16 + arow) * ROW64 + k0 + acolg * 8) * 2;
            ldm_x4(af[mb], aA + off);
        }
        uint32_t bfm[2][4];
        #pragma unroll
        for (int j = 0; j < 2; j++) {
            uint32_t off = (uint32_t)((wn * 32 + j * 16 + brow) * ROW64 + k0 + bcolg * 8) * 2;
            ldm_x4(bfm[j], aB + off);
        }
        #pragma unroll
        for (int mb = 0; mb < 2; mb++)
            #pragma unroll
            for (int j = 0; j < 2; j++)
                #pragma unroll
                for (int p = 0; p < 2; p++)
                    mma16816(acc[mb][j * 2 + p], af[mb], bfm[j][p * 2], bfm[j][p * 2 + 1]);
    }
}

template<bool BIAS, bool RES, typename OutT>
__global__ __launch_bounds__(128) void mm64gemm_kernel(
    const __half* __restrict__ A, const __half* __restrict__ B,
    const float* __restrict__ bias, const float* __restrict__ res,
    OutT* __restrict__ C, int M, int N, int K)
{
    extern __shared__ __align__(128) char smem[];
    uint32_t sb = smem_u32(smem);
    int tid = threadIdx.x;
    int wid = tid >> 5, lane = tid & 31;
    int wm = wid >> 1, wn = wid & 1;
    int bm = blockIdx.y * 64, bn = blockIdx.x * 64;

    float acc[2][4][4];
    #pragma unroll
    for (int a = 0; a < 2; a++)
        #pragma unroll
        for (int b = 0; b < 4; b++)
            #pragma unroll
            for (int c = 0; c < 4; c++) acc[a][b][c] = 0.0f;

    const int NC = K >> 5;
    mm64_load_stage(sb, A, B, bm, bn, K, 0, tid);
    CP_COMMIT();
    if (NC > 1) {
        mm64_load_stage(sb + STAGE64, A, B, bm, bn, K, 32, tid);
        CP_COMMIT();
    }
    for (int c = 0; c < NC; c++) {
        if (c + 2 < NC) CP_WAIT(1); else CP_WAIT(0);
        __syncthreads();
        if (c + 2 < NC) {
            mm64_load_stage(sb + ((c + 2) % MM_STAGES) * STAGE64, A, B, bm, bn, K, (c + 2) << 5, tid);
            CP_COMMIT();
        }
        mm64_compute_stage(sb + (c % MM_STAGES) * STAGE64, acc, wm, wn, lane);
    }

    int lane4 = lane >> 2;
    int lane2 = (lane & 3) << 1;
    #pragma unroll
    for (int mb = 0; mb < 2; mb++) {
        int r0 = bm + wm * 32 + mb * 16 + lane4;
        #pragma unroll
        for (int nb = 0; nb < 4; nb++) {
            int cc = bn + wn * 32 + nb * 8 + lane2;
            float* a = acc[mb][nb];
            float2 v0 = make_float2(a[0], a[1]);
            float2 v1 = make_float2(a[2], a[3]);
            if (BIAS) {
                float2 bb = *reinterpret_cast<const float2*>(bias + cc);
                v0.x += bb.x; v0.y += bb.y; v1.x += bb.x; v1.y += bb.y;
            }
            size_t o0 = (size_t)r0 * N + cc;
            size_t o1 = (size_t)(r0 + 8) * N + cc;
            if (RES) {
                float2 rr = *reinterpret_cast<const float2*>(res + o0);
                v0.x += rr.x; v0.y += rr.y;
                rr = *reinterpret_cast<const float2*>(res + o1);
                v1.x += rr.x; v1.y += rr.y;
            }
            store2(C + o0, v0);
            store2(C + o1, v1);
        }
    }
}

// ---------------------------------------------------------------------------
// Tensor-core flash attention (fp16 QKV, fp32 online softmax, split-KV)
// ---------------------------------------------------------------------------
#define FPAD 72
#define FQ_BYTES   (128 * FPAD * 2)
#define FKV_BYTES  (64 * FPAD * 2)
#define FSTAGE     (2 * FKV_BYTES)
#define FLASH_SMEM (FQ_BYTES + 2 * FSTAGE)

__device__ __forceinline__ void flash_load_tile(
    uint32_t stage, const __half* __restrict__ kvbase, int key0, int tid)
{
    #pragma unroll
    for (int i = 0; i < 4; i++) {
        int idx = i * 256 + tid;
        int o = idx >> 9;
        int key = (idx >> 3) & 63;
        int c = idx & 7;
        cp16(stage + o * FKV_BYTES + (key * FPAD + c * 8) * 2,
             kvbase + (size_t)(key0 + key) * (2 * DIM) + o * DIM + c * 8);
    }
}

__global__ __launch_bounds__(256) void flash_tc_kernel(
    const __half* __restrict__ Q, const __half* __restrict__ KV,
    float* __restrict__ part, int Nk, int nsplit)
{
    extern __shared__ __align__(128) char fsm[];
    uint32_t sb = smem_u32(fsm);
    const uint32_t Qs = sb;

    int bh = blockIdx.x;
    int b = bh >> 3, h = bh & 7;
    int split = blockIdx.y;
    int chunk = Nk / nsplit;
    int j0 = split * chunk;
    int ntiles = chunk >> 6;
    int tid = threadIdx.x, w = tid >> 5, lane = tid & 31;

    const __half* qbase  = Q  + (size_t)(b * LLAT) * DIM + h * DHEAD;
    const __half* kvbase = KV + (size_t)b * Nk * (2 * DIM) + h * DHEAD;

    #pragma unroll
    for (int i = 0; i < 4; i++) {
        int idx = i * 256 + tid;
        int row = idx >> 3, c = idx & 7;
        cp16(Qs + (row * FPAD + c * 8) * 2, qbase + (size_t)row * DIM + c * 8);
    }
    flash_load_tile(sb + FQ_BYTES, kvbase, j0, tid);
    CP_COMMIT();

    float O[8][4];
    #pragma unroll
    for (int j = 0; j < 8; j++)
        #pragma unroll
        for (int r = 0; r < 4; r++) O[j][r] = 0.0f;
    uint32_t qf[4][4];
    float m0 = -INFINITY, m1 = -INFINITY, l0 = 0.0f, l1 = 0.0f;

    int arow = lane & 15, acolg = lane >> 4;
    int brow = ((lane >> 4) << 3) + (lane & 7), bcolg = (lane >> 3) & 1;
    int krow = (((lane >> 3) & 1) << 3) + (lane & 7), ncolg = lane >> 4;
    const float k2 = ATT_SCALE * LOG2E;

    for (int t = 0; t < ntiles; t++) {
        if (t + 1 < ntiles) {
            flash_load_tile(sb + FQ_BYTES + ((t + 1) & 1) * FSTAGE, kvbase, j0 + (t + 1) * 64, tid);
            CP_COMMIT();
            CP_WAIT(1);
        } else {
            CP_WAIT(0);
        }
        __syncthreads();
        if (t == 0) {
            #pragma unroll
            for (int kk = 0; kk < 4; kk++)
                ldm_x4(qf[kk], Qs + ((w * 16 + arow) * FPAD + kk * 16 + acolg * 8) * 2);
        }
        uint32_t Kt = sb + FQ_BYTES + (t & 1) * FSTAGE;
        uint32_t Vt = Kt + FKV_BYTES;

        float S[8][4];
        #pragma unroll
        for (int j = 0; j < 8; j++)
            #pragma unroll
            for (int r = 0; r < 4; r++) S[j][r] = 0.0f;
        #pragma unroll
        for (int kk = 0; kk < 4; kk++) {
            #pragma unroll
            for (int jj = 0; jj < 4; jj++) {
                uint32_t bk[4];
                ldm_x4(bk, Kt + ((jj * 16 + brow) * FPAD + kk * 16 + bcolg * 8) * 2);
                mma16816(S[jj * 2],     qf[kk], bk[0], bk[1]);
                mma16816(S[jj * 2 + 1], qf[kk], bk[2], bk[3]);
            }
        }

        float t0 = -INFINITY, t1 = -INFINITY;
        #pragma unroll
        for (int j = 0; j < 8; j++) {
            t0 = fmaxf(t0, fmaxf(S[j][0], S[j][1]));
            t1 = fmaxf(t1, fmaxf(S[j][2], S[j][3]));
        }
        #pragma unroll
        for (int o = 1; o < 4; o <<= 1) {
            t0 = fmaxf(t0, __shfl_xor_sync(0xffffffffu, t0, o));
            t1 = fmaxf(t1, __shfl_xor_sync(0xffffffffu, t1, o));
        }
        float m0n = fmaxf(m0, t0 * ATT_SCALE);
        float m1n = fmaxf(m1, t1 * ATT_SCALE);
        float corr0 = ex2((m0 - m0n) * LOG2E);
        float corr1 = ex2((m1 - m1n) * LOG2E);
        l0 *= corr0; l1 *= corr1;
        #pragma unroll
        for (int j = 0; j < 8; j++) {
            O[j][0] *= corr0; O[j][1] *= corr0;
            O[j][2] *= corr1; O[j][3] *= corr1;
        }
        float mb0 = m0n * LOG2E, mb1 = m1n * LOG2E;
        float ps0 = 0.0f, ps1 = 0.0f;
        uint32_t ph[4][4];
        #pragma unroll
        for (int kk2 = 0; kk2 < 4; kk2++) {
            int ja = 2 * kk2, jb = ja + 1;
            float pa0 = ex2(fmaf(S[ja][0], k2, -mb0));
            float pa1 = ex2(fmaf(S[ja][1], k2, -mb0));
            float pa2 = ex2(fmaf(S[ja][2], k2, -mb1));
            float pa3 = ex2(fmaf(S[ja][3], k2, -mb1));
            float pb0 = ex2(fmaf(S[jb][0], k2, -mb0));
            float pb1 = ex2(fmaf(S[jb][1], k2, -mb0));
            float pb2 = ex2(fmaf(S[jb][2], k2, -mb1));
            float pb3 = ex2(fmaf(S[jb][3], k2, -mb1));
            ps0 += pa0 + pa1 + pb0 + pb1;
            ps1 += pa2 + pa3 + pb2 + pb3;
            ph[kk2][0] = packh2(pa0, pa1);
            ph[kk2][1] = packh2(pa2, pa3);
            ph[kk2][2] = packh2(pb0, pb1);
            ph[kk2][3] = packh2(pb2, pb3);
        }
        #pragma unroll
        for (int o = 1; o < 4; o <<= 1) {
            ps0 += __shfl_xor_sync(0xffffffffu, ps0, o);
            ps1 += __shfl_xor_sync(0xffffffffu, ps1, o);
        }
        l0 += ps0; l1 += ps1;
        m0 = m0n; m1 = m1n;

        #pragma unroll
        for (int kk2 = 0; kk2 < 4; kk2++) {
            #pragma unroll
            for (int jj = 0; jj < 4; jj++) {
                uint32_t bv[4];
                ldm_x4_t(bv, Vt + ((kk2 * 16 + krow) * FPAD + jj * 16 + ncolg * 8) * 2);
                mma16816(O[jj * 2],     ph[kk2], bv[0], bv[1]);
                mma16816(O[jj * 2 + 1], ph[kk2], bv[2], bv[3]);
            }
        }
        __syncthreads();
    }

    int r0 = w * 16 + (lane >> 2);
    size_t base0 = (((size_t)bh * LLAT + r0) * nsplit + split) * 66;
    size_t base1 = (((size_t)bh * LLAT + r0 + 8) * nsplit + split) * 66;
    if ((lane & 3) == 0) {
        part[base0] = m0; part[base0 + 1] = l0;
        part[base1] = m1; part[base1 + 1] = l1;
    }
    #pragma unroll
    for (int j = 0; j < 8; j++) {
        int col = j * 8 + (lane & 3) * 2;
        part[base0 + 2 + col]     = O[j][0];
        part[base0 + 2 + col + 1] = O[j][1];
        part[base1 + 2 + col]     = O[j][2];
        part[base1 + 2 + col + 1] = O[j][3];
    }
}

// ---------------------------------------------------------------------------
// Combine split-KV partials -> fp16 attention output
// ---------------------------------------------------------------------------
__global__ __launch_bounds__(64) void combine_f16_kernel(
    const float* __restrict__ part, __half* __restrict__ out, int nsplit)
{
    int idx = blockIdx.x;
    int i  = idx & (LLAT - 1);
    int bh = idx >> 7;
    int b = bh >> 3, h = bh & 7;
    int d = threadIdx.x;
    size_t base = (size_t)idx * nsplit * 66;
    float M = -INFINITY;
    for (int s = 0; s < nsplit; s++) M = fmaxf(M, part[base + (size_t)s * 66]);
    float L = 0.0f, o = 0.0f;
    for (int s = 0; s < nsplit; s++) {
        float a = __expf(part[base + (size_t)s * 66] - M);
        L += a * part[base + (size_t)s * 66 + 1];
        o += a * part[base + (size_t)s * 66 + 2 + d];
    }
    out[((size_t)(b * LLAT + i)) * DIM + h * DHEAD + d] = __float2half(o / L);
}

// ---------------------------------------------------------------------------
// LayerNorm (last dim 512) -> fp16
// ---------------------------------------------------------------------------
__global__ __launch_bounds__(128) void ln_f16_kernel(
    const float* __restrict__ x, const float* __restrict__ w,
    const float* __restrict__ b, __half* __restrict__ out)
{
    int row = blockIdx.x;
    int t = threadIdx.x;
    float4 v = reinterpret_cast<const float4*>(x + (size_t)row * DIM)[t];
    float s  = v.x + v.y + v.z + v.w;
    float ss = v.x*v.x + v.y*v.y + v.z*v.z + v.w*v.w;
    #pragma unroll
    for (int o = 16; o > 0; o >>= 1) {
        s  += __shfl_xor_sync(0xffffffffu, s,  o);
        ss += __shfl_xor_sync(0xffffffffu, ss, o);
    }
    __shared__ float rs[4], rss[4];
    int warp = t >> 5;
    if ((t & 31) == 0) { rs[warp] = s; rss[warp] = ss; }
    __syncthreads();
    s  = rs[0] + rs[1] + rs[2] + rs[3];
    ss = rss[0] + rss[1] + rss[2] + rss[3];
    float mu  = s * (1.0f / DIM);
    float var = ss * (1.0f / DIM) - mu * mu;
    float inv = rsqrtf(var + 1e-5f);
    float4 wv = reinterpret_cast<const float4*>(w)[t];
    float4 bv = reinterpret_cast<const float4*>(b)[t];
    __half2 h0 = __floats2half2_rn((v.x - mu) * inv * wv.x + bv.x,
                                   (v.y - mu) * inv * wv.y + bv.y);
    __half2 h1 = __floats2half2_rn((v.z - mu) * inv * wv.z + bv.z,
                                   (v.w - mu) * inv * wv.w + bv.w);
    __half2* op = reinterpret_cast<__half2*>(out + (size_t)row * DIM + t * 4);
    op[0] = h0; op[1] = h1;
}

// ---------------------------------------------------------------------------
// Batched weight convert + transpose: all 10 matrices, one launch.
// ---------------------------------------------------------------------------
__global__ __launch_bounds__(256) void wconv_all_kernel(
    const float* w0, const float* w1, const float* w2, const float* w3,
    const float* w4, const float* w5, const float* w6, const float* w7,
    const float* w8, const float* w9, __half* __restrict__ out)
{
    const int   cum[10]  = {256, 768, 1024, 3072, 4096, 4352, 4864, 5120, 7168, 8192};
    const int   Ks[10]   = {512, 512, 512, 512, 2048, 512, 512, 512, 512, 2048};
    const int   Ns[10]   = {512, 1024, 512, 4096, 512, 512, 1024, 512, 4096, 512};
    const size_t offs[10] = {WO_CAQ, WO_CAKV, WO_CAO, WO_CF1, WO_CF2,
                             WO_SAQ, WO_SAKV, WO_SAO, WO_LF1, WO_LF2};
    const float* ws[10] = {w0, w1, w2, w3, w4, w5, w6, w7, w8, w9};

    int bid = blockIdx.x;
    int mi = 0;
    #pragma unroll
    for (int i = 0; i < 9; i++) if (bid >= cum[i]) mi = i + 1;
    int base = (mi == 0) ? 0 : cum[mi - 1];
    int t = bid - base;
    int K = Ks[mi], N = Ns[mi];
    int tilesX = N >> 5;
    int bx = t % tilesX, by = t / tilesX;
    const float* W = ws[mi];
    __half* O = out + offs[mi];

    __shared__ float tile[32][33];
    int tx = threadIdx.x & 31, ty = threadIdx.x >> 5;
    int x = bx * 32 + tx;
    int y0 = by * 32;
    #pragma unroll
    for (int j = ty; j < 32; j += 8)
        tile[j][tx] = W[(size_t)(y0 + j) * N + x];
    __syncthreads();
    #pragma unroll
    for (int j = ty; j < 32; j += 8) {
        int n = bx * 32 + j;
        int k = y0 + tx;
        O[(size_t)n * K + k] = __float2half(tile[tx][j]);
    }
}

// ---------------------------------------------------------------------------
// GEGLU (exact erf, fp16 in) -> fp16
// ---------------------------------------------------------------------------
__global__ __launch_bounds__(256) void geglu_f16_kernel(
    const __half* __restrict__ hbuf, __half* __restrict__ out)
{
    int idx = blockIdx.x * blockDim.x + threadIdx.x;
    int row = idx >> 11;
    int c   = idx & 2047;
    float a = __half2float(hbuf[(size_t)row * (2 * FFD) + c]);
    float g = __half2float(hbuf[(size_t)row * (2 * FFD) + FFD + c]);
    float y = a * (0.5f * g * (1.0f + erff(g * 0.70710678118654752f)));
    out[idx] = __float2half(y);
}

// ---------------------------------------------------------------------------
// Host orchestration
// ---------------------------------------------------------------------------
extern "C" void kernel_launch(void* const* d_in, const int* in_sizes, int n_in,
                              void* d_out, int out_size)
{
    (void)in_sizes; (void)n_in; (void)out_size;
    const float* context = (const float*)d_in[0];
    const float* latents = (const float*)d_in[1];
    const float* ca_ln_w  = (const float*)d_in[2];
    const float* ca_ln_b  = (const float*)d_in[3];
    const float* ca_lnc_w = (const float*)d_in[4];
    const float* ca_lnc_b = (const float*)d_in[5];
    const float* ca_wq  = (const float*)d_in[6];
    const float* ca_wkv = (const float*)d_in[7];
    const float* ca_wo  = (const float*)d_in[8];
    const float* ca_bo  = (const float*)d_in[9];
    const float* cf_ln_w = (const float*)d_in[10];
    const float* cf_ln_b = (const float*)d_in[11];
    const float* cf_w1 = (const float*)d_in[12];
    const float* cf_b1 = (const float*)d_in[13];
    const float* cf_w2 = (const float*)d_in[14];
    const float* cf_b2 = (const float*)d_in[15];
    const float* sa_ln_w = (const float*)d_in[16];
    const float* sa_ln_b = (const float*)d_in[17];
    const float* sa_wq  = (const float*)d_in[18];
    const float* sa_wkv = (const float*)d_in[19];
    const float* sa_wo  = (const float*)d_in[20];
    const float* sa_bo  = (const float*)d_in[21];
    const float* lf_ln_w = (const float*)d_in[22];
    const float* lf_ln_b = (const float*)d_in[23];
    const float* lf_w1 = (const float*)d_in[24];
    const float* lf_b1 = (const float*)d_in[25];
    const float* lf_w2 = (const float*)d_in[26];
    const float* lf_b2 = (const float*)d_in[27];

    void* sp = nullptr;
    cudaGetSymbolAddress(&sp, g_scratch);
    unsigned char* S = (unsigned char*)sp;
    __half* kvb = (__half*)(S + SB_KVB);
    __half* hb  = (__half*)(S + SB_HB);
    float* pb   = (float*)(S + SB_PART);
    __half* cnh = (__half*)(S + SB_CNH);
    __half* wh  = (__half*)(S + SB_WH);
    __half* xnh = (__half*)(S + SB_XNH);
    __half* qbh = (__half*)(S + SB_QB);
    __half* aobh= (__half*)(S + SB_AOBH);
    __half* ggh = (__half*)(S + SB_GGH);
    float* x1   = (float*)(S + SB_X1);
    float* x2   = (float*)(S + SB_X2);
    float* x3   = (float*)(S + SB_X3);

    cudaFuncSetAttribute(mmgemm_kernel<false,false,__half>, cudaFuncAttributeMaxDynamicSharedMemorySize, MM_SMEM);
    cudaFuncSetAttribute(mmgemm_kernel<true,false,__half>,  cudaFuncAttributeMaxDynamicSharedMemorySize, MM_SMEM);
    cudaFuncSetAttribute(flash_tc_kernel, cudaFuncAttributeMaxDynamicSharedMemorySize, FLASH_SMEM);

    const int rowsL = BATCH * LLAT;   // 1024
    const int rowsC = BATCH * NCTX;   // 32768

    // ---- launch 0: all weight converts (one kernel) ----
    wconv_all_kernel<<<8192, 256>>>(ca_wq, ca_wkv, ca_wo, cf_w1, cf_w2,
                                    sa_wq, sa_wkv, sa_wo, lf_w1, lf_w2, wh);

    // ---- cross attention ----
    ln_f16_kernel<<<rowsC, 128>>>(context, ca_lnc_w, ca_lnc_b, cnh);
    ln_f16_kernel<<<rowsL, 128>>>(latents, ca_ln_w, ca_ln_b, xnh);
    mmgemm_kernel<false,false,__half><<<dim3(8, 256), 256, MM_SMEM>>>(
        cnh, wh + WO_CAKV, nullptr, nullptr, kvb, rowsC, 1024, 512);
    mm64gemm_kernel<false,false,__half><<<dim3(8, 16), 128, MM64_SMEM>>>(
        xnh, wh + WO_CAQ, nullptr, nullptr, qbh, rowsL, 512, 512);
    flash_tc_kernel<<<dim3(64, 8), 256, FLASH_SMEM>>>(qbh, kvb, pb, NCTX, 8);
    combine_f16_kernel<<<8192, 64>>>(pb, aobh, 8);
    mm64gemm_kernel<true,true,float><<<dim3(8, 16), 128, MM64_SMEM>>>(
        aobh, wh + WO_CAO, ca_bo, latents, x1, rowsL, 512, 512);

    // ---- cross FFN (GEGLU) ----
    ln_f16_kernel<<<rowsL, 128>>>(x1, cf_ln_w, cf_ln_b, xnh);
    mmgemm_kernel<true,false,__half><<<dim3(32, 8), 256, MM_SMEM>>>(
        xnh, wh + WO_CF1, cf_b1, nullptr, hb, rowsL, 4096, 512);
    geglu_f16_kernel<<<8192, 256>>>(hb, ggh);
    mm64gemm_kernel<true,true,float><<<dim3(8, 16), 128, MM64_SMEM>>>(
        ggh, wh + WO_CF2, cf_b2, x1, x2, rowsL, 512, 2048);

    // ---- latent self-attention ----
    ln_f16_kernel<<<rowsL, 128>>>(x2, sa_ln_w, sa_ln_b, xnh);
    mm64gemm_kernel<false,false,__half><<<dim3(8, 16), 128, MM64_SMEM>>>(
        xnh, wh + WO_SAQ, nullptr, nullptr, qbh, rowsL, 512, 512);
    mm64gemm_kernel<false,false,__half><<<dim3(16, 16), 128, MM64_SMEM>>>(
        xnh, wh + WO_SAKV, nullptr, nullptr, kvb, rowsL, 1024, 512);
    flash_tc_kernel<<<dim3(64, 2), 256, FLASH_SMEM>>>(qbh, kvb, pb, LLAT, 2);
    combine_f16_kernel<<<8192, 64>>>(pb, aobh, 2);
    mm64gemm_kernel<true,true,float><<<dim3(8, 16), 128, MM64_SMEM>>>(
        aobh, wh + WO_SAO, sa_bo, x2, x3, rowsL, 512, 512);

    // ---- latent FFN (GEGLU) ----
    ln_f16_kernel<<<rowsL, 128>>>(x3, lf_ln_w, lf_ln_b, xnh);
    mmgemm_kernel<true,false,__half><<<dim3(32, 8), 256, MM_SMEM>>>(
        xnh, wh + WO_LF1, lf_b1, nullptr, hb, rowsL, 4096, 512);
    geglu_f16_kernel<<<8192, 256>>>(hb, ggh);
    mm64gemm_kernel<true,true,float><<<dim3(8, 16), 128, MM64_SMEM>>>(
        ggh, wh + WO_LF2, lf_b2, x3, (float*)d_out, rowsL, 512, 2048);
}